// round 1
// baseline (speedup 1.0000x reference)
#include <cuda_runtime.h>
#include <math.h>

// ---------------- problem constants ----------------
#define BATCH 512
#define NH 4
#define KD 16          // key dim
#define DD 64          // value dim per head
#define DIM 256        // NH*DD
#define QO 96          // qkv out = 2*KD + DD
#define RESX 14
#define NPIX 196       // 14*14
#define VSTRIDE 68     // padded v row stride (196 x 68)

typedef unsigned long long ull;

// global scratch: relu'd concat of head outputs (B, 256, 196)
__device__ float g_cat[(size_t)BATCH * DIM * NPIX];

// ---------------- f32x2 helpers ----------------
__device__ __forceinline__ void fma2(ull &d, ull a, ull b) {
    asm("fma.rn.f32x2 %0, %1, %2, %0;" : "+l"(d) : "l"(a), "l"(b));
}
__device__ __forceinline__ ull pk2(float lo, float hi) {
    ull r; asm("mov.b64 %0, {%1, %2};" : "=l"(r) : "f"(lo), "f"(hi)); return r;
}
__device__ __forceinline__ void unpk2(ull v, float &lo, float &hi) {
    asm("mov.b64 {%0, %1}, %2;" : "=f"(lo), "=f"(hi) : "l"(v));
}

// ---------------- smem layout (floats) ----------------
// feat   : 64*196        = 12544   @ 0
// qbuf   : 16*196        = 3136    @ 12544
// kbuf   : 16*196        = 3136    @ 15680
// qgbuf  : 16*196        = 3136    @ 18816
// vbuf   : 196*68        = 13328   @ 21952   ([m][d], padded)
// wq     : 96*64         = 6144    @ 35280
// dww    : 16*25         = 400     @ 41424
// abh    : 196                     @ 41824
// qsc    : 96                      @ 42020
// qbi    : 96                      @ 42116
// dsc    : 16                      @ 42212
// dbi    : 16                      @ 42228
// (end floats 42244)
// a2 (ull): 8*4*196 = 6272 ull     @ byte 168976
#define OFF_FEAT  0
#define OFF_Q     12544
#define OFF_K     15680
#define OFF_QG    18816
#define OFF_V     21952
#define OFF_WQ    35280
#define OFF_DWW   41424
#define OFF_ABH   41824
#define OFF_QSC   42020
#define OFF_QBI   42116
#define OFF_DSC   42212
#define OFF_DBI   42228
#define OFF_A2_BYTES 168976
#define SMEM1_BYTES (168976 + 8*4*196*8)   // 219152

__global__ void __launch_bounds__(256, 1)
cascade_kernel(const float* __restrict__ x,
               const float* __restrict__ qkv_w,
               const float* __restrict__ qkv_scale,
               const float* __restrict__ qkv_bias,
               const float* __restrict__ dw_w,
               const float* __restrict__ dw_scale,
               const float* __restrict__ dw_bias,
               const float* __restrict__ attention_biases,
               const int*   __restrict__ bias_idxs)
{
    extern __shared__ float sm[];
    float* feat  = sm + OFF_FEAT;
    float* qbuf  = sm + OFF_Q;
    float* kbuf  = sm + OFF_K;
    float* qgbuf = sm + OFF_QG;
    float* vbuf  = sm + OFF_V;
    float* wq    = sm + OFF_WQ;
    float* dww   = sm + OFF_DWW;
    float* abh   = sm + OFF_ABH;
    float* qsc   = sm + OFF_QSC;
    float* qbi   = sm + OFF_QBI;
    float* dsc   = sm + OFF_DSC;
    float* dbi   = sm + OFF_DBI;
    ull*   a2    = (ull*)((char*)sm + OFF_A2_BYTES);

    const int b    = blockIdx.x;
    const int tid  = threadIdx.x;
    const int warp = tid >> 5;
    const int lane = tid & 31;

    for (int i = 0; i < NH; i++) {
        // ---------- Phase A: feat accumulate + per-head weight staging ----------
        {
            const float* xb = x + ((size_t)b * DIM + i * DD) * NPIX;
            if (i == 0) {
                for (int idx = tid; idx < DD * NPIX; idx += 256) feat[idx] = xb[idx];
            } else {
                for (int idx = tid; idx < DD * NPIX; idx += 256) feat[idx] += xb[idx];
            }
            for (int idx = tid; idx < QO * 64; idx += 256) wq[idx] = qkv_w[i * QO * 64 + idx];
            for (int idx = tid; idx < 16 * 25; idx += 256) dww[idx] = dw_w[i * 400 + idx];
            if (tid < NPIX) abh[tid] = attention_biases[i * NPIX + tid];
            if (tid < QO) { qsc[tid] = qkv_scale[i * QO + tid]; qbi[tid] = qkv_bias[i * QO + tid]; }
            if (tid < KD) { dsc[tid] = dw_scale[i * KD + tid]; dbi[tid] = dw_bias[i * KD + tid]; }
        }
        __syncthreads();

        // ---------- Phase B: QKV GEMM (96 x 196 = wq[96x64] @ feat[64x196]) ----------
        // tasks: 24 o-blocks(4) x 98 n-blocks(2)
        for (int t = tid; t < 24 * 98; t += 256) {
            int ob = t / 98;
            int nb = t - ob * 98;
            int o0 = ob * 4, n0 = nb * 2;
            ull acc0 = 0, acc1 = 0, acc2 = 0, acc3 = 0;
            #pragma unroll 8
            for (int c = 0; c < 64; c++) {
                float2 f = *(const float2*)&feat[c * NPIX + n0];
                ull fp = pk2(f.x, f.y);
                float w0 = wq[(o0 + 0) * 64 + c];
                float w1 = wq[(o0 + 1) * 64 + c];
                float w2 = wq[(o0 + 2) * 64 + c];
                float w3 = wq[(o0 + 3) * 64 + c];
                fma2(acc0, pk2(w0, w0), fp);
                fma2(acc1, pk2(w1, w1), fp);
                fma2(acc2, pk2(w2, w2), fp);
                fma2(acc3, pk2(w3, w3), fp);
            }
            ull accs[4] = {acc0, acc1, acc2, acc3};
            #pragma unroll
            for (int j = 0; j < 4; j++) {
                int o = o0 + j;
                float y0, y1;
                unpk2(accs[j], y0, y1);
                float s = qsc[o], bb = qbi[o];
                y0 = y0 * s + bb;
                y1 = y1 * s + bb;
                if (o < KD) {
                    qbuf[o * NPIX + n0] = y0; qbuf[o * NPIX + n0 + 1] = y1;
                } else if (o < 2 * KD) {
                    int oo = o - KD;
                    kbuf[oo * NPIX + n0] = y0; kbuf[oo * NPIX + n0 + 1] = y1;
                } else {
                    int oo = o - 2 * KD;
                    vbuf[n0 * VSTRIDE + oo] = y0;
                    vbuf[(n0 + 1) * VSTRIDE + oo] = y1;
                }
            }
        }
        __syncthreads();

        // ---------- Phase C: depthwise 5x5 conv + affine + exact GELU + residual ----------
        for (int t = tid; t < KD * NPIX; t += 256) {
            int c = t / NPIX;
            int p = t - c * NPIX;
            int py = p / RESX, px = p - py * RESX;
            float s = 0.f;
            #pragma unroll
            for (int dy = 0; dy < 5; dy++) {
                int yy = py + dy - 2;
                if (yy < 0 || yy >= RESX) continue;
                #pragma unroll
                for (int dx = 0; dx < 5; dx++) {
                    int xx = px + dx - 2;
                    if (xx < 0 || xx >= RESX) continue;
                    s += dww[c * 25 + dy * 5 + dx] * qbuf[c * NPIX + yy * RESX + xx];
                }
            }
            float dq = s * dsc[c] + dbi[c];
            float g = 0.5f * dq * (1.0f + erff(dq * 0.70710678118654752440f));
            qgbuf[t] = g + qbuf[t];
        }
        __syncthreads();

        // ---------- Phase D: attention, per-warp 4-row blocks (49 blocks) ----------
        const ull* a2row = a2 + warp * 4 * NPIX;
        for (int rb = warp; rb < 49; rb += 8) {
            int n0 = rb * 4;
            // preload q (post-gelu) rows, packed in row pairs
            ull qgr2[KD][2];
            #pragma unroll
            for (int c = 0; c < KD; c++) {
                const float* qr = &qgbuf[c * NPIX + n0];
                qgr2[c][0] = pk2(qr[0], qr[1]);
                qgr2[c][1] = pk2(qr[2], qr[3]);
            }
            // QK^T + bias (lane-strided over m)
            float sv[4][7];
            #pragma unroll
            for (int j = 0; j < 7; j++) {
                int m = lane + 32 * j;
                if (m < NPIX) {
                    ull t0 = 0, t1 = 0;
                    #pragma unroll
                    for (int c = 0; c < KD; c++) {
                        float kk = kbuf[c * NPIX + m];
                        ull kd = pk2(kk, kk);
                        fma2(t0, qgr2[c][0], kd);
                        fma2(t1, qgr2[c][1], kd);
                    }
                    float s00, s01, s10, s11;
                    unpk2(t0, s00, s01);
                    unpk2(t1, s10, s11);
                    sv[0][j] = s00 * 0.25f + abh[bias_idxs[(n0 + 0) * NPIX + m]];
                    sv[1][j] = s01 * 0.25f + abh[bias_idxs[(n0 + 1) * NPIX + m]];
                    sv[2][j] = s10 * 0.25f + abh[bias_idxs[(n0 + 2) * NPIX + m]];
                    sv[3][j] = s11 * 0.25f + abh[bias_idxs[(n0 + 3) * NPIX + m]];
                } else {
                    sv[0][j] = -1e30f; sv[1][j] = -1e30f;
                    sv[2][j] = -1e30f; sv[3][j] = -1e30f;
                }
            }
            // softmax per row; store probabilities duplicated as f32x2
            #pragma unroll
            for (int r = 0; r < 4; r++) {
                float mx = -1e30f;
                #pragma unroll
                for (int j = 0; j < 7; j++) mx = fmaxf(mx, sv[r][j]);
                #pragma unroll
                for (int off = 16; off; off >>= 1)
                    mx = fmaxf(mx, __shfl_xor_sync(0xffffffffu, mx, off));
                float sum = 0.f;
                #pragma unroll
                for (int j = 0; j < 7; j++) {
                    float e = expf(sv[r][j] - mx);
                    sv[r][j] = e;
                    sum += e;
                }
                #pragma unroll
                for (int off = 16; off; off >>= 1)
                    sum += __shfl_xor_sync(0xffffffffu, sum, off);
                float inv = 1.0f / sum;
                #pragma unroll
                for (int j = 0; j < 7; j++) {
                    int m = lane + 32 * j;
                    if (m < NPIX) {
                        float p = sv[r][j] * inv;
                        a2[(warp * 4 + r) * NPIX + m] = pk2(p, p);
                    }
                }
            }
            __syncwarp();
            // AV: lane owns d = 2*lane, 2*lane+1
            ull acc[4] = {0, 0, 0, 0};
            #pragma unroll 4
            for (int m = 0; m < NPIX; m++) {
                ull vp = *(const ull*)&vbuf[m * VSTRIDE + 2 * lane];
                #pragma unroll
                for (int r = 0; r < 4; r++)
                    fma2(acc[r], a2row[r * NPIX + m], vp);
            }
            #pragma unroll
            for (int r = 0; r < 4; r++) {
                float o0, o1;
                unpk2(acc[r], o0, o1);
                int n = n0 + r;
                feat[(2 * lane) * NPIX + n] = o0;
                feat[(2 * lane + 1) * NPIX + n] = o1;
            }
            __syncwarp();
        }
        __syncthreads();

        // ---------- export relu(feat) -> g_cat (coalesced) ----------
        {
            float* gc = g_cat + ((size_t)b * DIM + i * DD) * NPIX;
            for (int idx = tid; idx < DD * NPIX; idx += 256)
                gc[idx] = fmaxf(feat[idx], 0.f);
        }
        __syncthreads();
    }
}

// ---------------- proj kernel: out = affine(proj_w @ cat) ----------------
// grid = 512*7 CTAs (one batch x 28-pixel tile), 256 threads
// smem: catsm 256*28 floats (7168) + Wsm 64*258 floats (16512) = 94720 B
#define PROJ_CAT 7168
#define PROJ_W_OFF 7168
#define SMEM2_BYTES ((7168 + 64*258) * 4)

__global__ void __launch_bounds__(256)
proj_kernel(const float* __restrict__ proj_w,
            const float* __restrict__ proj_scale,
            const float* __restrict__ proj_bias,
            float* __restrict__ out)
{
    extern __shared__ float sm[];
    float* catsm = sm;
    float* Wsm = sm + PROJ_W_OFF;

    int b = blockIdx.x / 7;
    int tile = blockIdx.x - b * 7;
    int p0 = tile * 28;
    int tid = threadIdx.x;

    const float* gc = g_cat + (size_t)b * DIM * NPIX;
    for (int idx = tid; idx < DIM * 28; idx += 256) {
        int c = idx / 28, n = idx - c * 28;
        catsm[idx] = gc[c * NPIX + p0 + n];
    }
    __syncthreads();

    int nb = tid & 3, ob = tid >> 2;      // warp: 4 nb x 8 ob (multicast-friendly)
    int o0 = ob * 4, n0 = nb * 7;

    ull acc[2][7];
    #pragma unroll
    for (int p = 0; p < 2; p++)
        #pragma unroll
        for (int k = 0; k < 7; k++) acc[p][k] = 0;

    for (int c0 = 0; c0 < 256; c0 += 64) {
        for (int idx = tid; idx < 64 * 256; idx += 256) {
            int o = idx >> 6, cc = idx & 63;
            Wsm[cc * 258 + o] = proj_w[o * 256 + c0 + cc];
        }
        __syncthreads();
        #pragma unroll 4
        for (int cc = 0; cc < 64; cc++) {
            ull w01 = *(const ull*)&Wsm[cc * 258 + o0];
            ull w23 = *(const ull*)&Wsm[cc * 258 + o0 + 2];
            const float* cp = &catsm[(c0 + cc) * 28 + n0];
            #pragma unroll
            for (int k = 0; k < 7; k++) {
                ull fd = pk2(cp[k], cp[k]);
                fma2(acc[0][k], w01, fd);
                fma2(acc[1][k], w23, fd);
            }
        }
        __syncthreads();
    }

    // epilogue: affine, stage through smem (reuse catsm) for coalesced stores
    float* outsm = catsm;
    #pragma unroll
    for (int p = 0; p < 2; p++) {
        int oA = o0 + 2 * p, oB = oA + 1;
        float sA = proj_scale[oA], bA = proj_bias[oA];
        float sB = proj_scale[oB], bB = proj_bias[oB];
        #pragma unroll
        for (int k = 0; k < 7; k++) {
            float v0, v1;
            unpk2(acc[p][k], v0, v1);
            outsm[oA * 28 + n0 + k] = v0 * sA + bA;
            outsm[oB * 28 + n0 + k] = v1 * sB + bB;
        }
    }
    __syncthreads();
    float* ob_out = out + (size_t)b * DIM * NPIX + p0;
    for (int idx = tid; idx < DIM * 28; idx += 256) {
        int c = idx / 28, n = idx - c * 28;
        ob_out[c * NPIX + n] = outsm[idx];
    }
}

extern "C" void kernel_launch(void* const* d_in, const int* in_sizes, int n_in,
                              void* d_out, int out_size)
{
    (void)in_sizes; (void)n_in; (void)out_size;
    const float* x          = (const float*)d_in[0];
    const float* qkv_w      = (const float*)d_in[1];
    const float* qkv_scale  = (const float*)d_in[2];
    const float* qkv_bias   = (const float*)d_in[3];
    const float* dw_w       = (const float*)d_in[4];
    const float* dw_scale   = (const float*)d_in[5];
    const float* dw_bias    = (const float*)d_in[6];
    const float* proj_w     = (const float*)d_in[7];
    const float* proj_scale = (const float*)d_in[8];
    const float* proj_bias  = (const float*)d_in[9];
    const float* attn_b     = (const float*)d_in[10];
    const int*   bias_idxs  = (const int*)d_in[11];
    float* out = (float*)d_out;

    cudaFuncSetAttribute(cascade_kernel, cudaFuncAttributeMaxDynamicSharedMemorySize, SMEM1_BYTES);
    cudaFuncSetAttribute(proj_kernel, cudaFuncAttributeMaxDynamicSharedMemorySize, SMEM2_BYTES);

    cascade_kernel<<<BATCH, 256, SMEM1_BYTES>>>(x, qkv_w, qkv_scale, qkv_bias,
                                                dw_w, dw_scale, dw_bias,
                                                attn_b, bias_idxs);
    proj_kernel<<<BATCH * 7, 256, SMEM2_BYTES>>>(proj_w, proj_scale, proj_bias, out);
}

// round 3
// speedup vs baseline: 1.3008x; 1.3008x over previous
#include <cuda_runtime.h>
#include <math.h>
#include <cstdint>

// ---------------- problem constants ----------------
#define BATCH 512
#define NH 4
#define KD 16          // key dim
#define DD 64          // value dim per head
#define DIM 256        // NH*DD
#define QO 96          // qkv out = 2*KD + DD
#define RESX 14
#define NPIX 196       // 14*14
#define VSTRIDE 68     // padded v row stride (196 x 68)

typedef unsigned long long ull;

// global scratch: relu'd concat of head outputs, PIXEL-MAJOR: [b*196+n][c], tf32-rounded
__device__ __align__(128) float g_cat_t[(size_t)BATCH * NPIX * DIM];
// tf32-rounded proj weights
__device__ __align__(128) float g_wt[DIM * DIM];

// ---------------- f32x2 helpers ----------------
__device__ __forceinline__ void fma2(ull &d, ull a, ull b) {
    asm("fma.rn.f32x2 %0, %1, %2, %0;" : "+l"(d) : "l"(a), "l"(b));
}
__device__ __forceinline__ ull pk2(float lo, float hi) {
    ull r; asm("mov.b64 %0, {%1, %2};" : "=l"(r) : "f"(lo), "f"(hi)); return r;
}
__device__ __forceinline__ void unpk2(ull v, float &lo, float &hi) {
    asm("mov.b64 {%0, %1}, %2;" : "=f"(lo), "=f"(hi) : "l"(v));
}
__device__ __forceinline__ float to_tf32(float x) {
    float r; asm("cvt.rna.satfinite.tf32.f32 %0, %1;" : "=f"(r) : "f"(x)); return r;
}
__device__ __forceinline__ uint32_t smem_u32(const void* p) {
    uint32_t a;
    asm("{ .reg .u64 t; cvta.to.shared.u64 t, %1; cvt.u32.u64 %0, t; }" : "=r"(a) : "l"(p));
    return a;
}

// ---------------- cp.async helpers ----------------
#define CP_ASYNC16(dst_u32, src_ptr) \
    asm volatile("cp.async.cg.shared.global [%0], [%1], 16;" :: "r"(dst_u32), "l"(src_ptr))
#define CP_COMMIT() asm volatile("cp.async.commit_group;" ::: "memory")
#define CP_WAIT0()  asm volatile("cp.async.wait_group 0;" ::: "memory")

// ---------------- mma.sync tf32 m16n8k8 ----------------
__device__ __forceinline__ void mma_tf32(float* d, const uint32_t* a, const uint32_t* b) {
    asm volatile(
        "mma.sync.aligned.m16n8k8.row.col.f32.tf32.tf32.f32 "
        "{%0,%1,%2,%3}, {%4,%5,%6,%7}, {%8,%9}, {%0,%1,%2,%3};"
        : "+f"(d[0]), "+f"(d[1]), "+f"(d[2]), "+f"(d[3])
        : "r"(a[0]), "r"(a[1]), "r"(a[2]), "r"(a[3]), "r"(b[0]), "r"(b[1]));
}

// ---------------- smem layout for cascade kernel (floats) ----------------
#define OFF_FEAT  0
#define OFF_Q     12544
#define OFF_K     15680
#define OFF_QG    18816
#define OFF_V     21952
#define OFF_WQ    35280
#define OFF_DWW   41424
#define OFF_ABH   41824
#define OFF_QSC   42020
#define OFF_QBI   42116
#define OFF_DSC   42212
#define OFF_DBI   42228
#define OFF_A2_BYTES 168976
#define SMEM1_BYTES (168976 + 8*4*196*8)   // 219152

__global__ void __launch_bounds__(256, 1)
cascade_kernel(const float* __restrict__ x,
               const float* __restrict__ qkv_w,
               const float* __restrict__ qkv_scale,
               const float* __restrict__ qkv_bias,
               const float* __restrict__ dw_w,
               const float* __restrict__ dw_scale,
               const float* __restrict__ dw_bias,
               const float* __restrict__ attention_biases,
               const int*   __restrict__ bias_idxs)
{
    extern __shared__ float sm[];
    float* feat  = sm + OFF_FEAT;
    float* qbuf  = sm + OFF_Q;
    float* kbuf  = sm + OFF_K;
    float* qgbuf = sm + OFF_QG;
    float* vbuf  = sm + OFF_V;
    float* wq    = sm + OFF_WQ;
    float* dww   = sm + OFF_DWW;
    float* abh   = sm + OFF_ABH;
    float* qsc   = sm + OFF_QSC;
    float* qbi   = sm + OFF_QBI;
    float* dsc   = sm + OFF_DSC;
    float* dbi   = sm + OFF_DBI;
    ull*   a2    = (ull*)((char*)sm + OFF_A2_BYTES);

    const int b    = blockIdx.x;
    const int tid  = threadIdx.x;
    const int warp = tid >> 5;
    const int lane = tid & 31;

    for (int i = 0; i < NH; i++) {
        // ---------- Phase A: feat accumulate + per-head weight staging ----------
        {
            const float* xb = x + ((size_t)b * DIM + i * DD) * NPIX;
            if (i == 0) {
                for (int idx = tid; idx < DD * NPIX; idx += 256) feat[idx] = xb[idx];
            } else {
                for (int idx = tid; idx < DD * NPIX; idx += 256) feat[idx] += xb[idx];
            }
            for (int idx = tid; idx < QO * 64; idx += 256) wq[idx] = qkv_w[i * QO * 64 + idx];
            for (int idx = tid; idx < 16 * 25; idx += 256) dww[idx] = dw_w[i * 400 + idx];
            if (tid < NPIX) abh[tid] = attention_biases[i * NPIX + tid];
            if (tid < QO) { qsc[tid] = qkv_scale[i * QO + tid]; qbi[tid] = qkv_bias[i * QO + tid]; }
            if (tid < KD) { dsc[tid] = dw_scale[i * KD + tid]; dbi[tid] = dw_bias[i * KD + tid]; }
        }
        __syncthreads();

        // ---------- Phase B: QKV GEMM ----------
        for (int t = tid; t < 24 * 98; t += 256) {
            int ob = t / 98;
            int nb = t - ob * 98;
            int o0 = ob * 4, n0 = nb * 2;
            ull acc0 = 0, acc1 = 0, acc2 = 0, acc3 = 0;
            #pragma unroll 8
            for (int c = 0; c < 64; c++) {
                float2 f = *(const float2*)&feat[c * NPIX + n0];
                ull fp = pk2(f.x, f.y);
                float w0 = wq[(o0 + 0) * 64 + c];
                float w1 = wq[(o0 + 1) * 64 + c];
                float w2 = wq[(o0 + 2) * 64 + c];
                float w3 = wq[(o0 + 3) * 64 + c];
                fma2(acc0, pk2(w0, w0), fp);
                fma2(acc1, pk2(w1, w1), fp);
                fma2(acc2, pk2(w2, w2), fp);
                fma2(acc3, pk2(w3, w3), fp);
            }
            ull accs[4] = {acc0, acc1, acc2, acc3};
            #pragma unroll
            for (int j = 0; j < 4; j++) {
                int o = o0 + j;
                float y0, y1;
                unpk2(accs[j], y0, y1);
                float s = qsc[o], bb = qbi[o];
                y0 = y0 * s + bb;
                y1 = y1 * s + bb;
                if (o < KD) {
                    qbuf[o * NPIX + n0] = y0; qbuf[o * NPIX + n0 + 1] = y1;
                } else if (o < 2 * KD) {
                    int oo = o - KD;
                    kbuf[oo * NPIX + n0] = y0; kbuf[oo * NPIX + n0 + 1] = y1;
                } else {
                    int oo = o - 2 * KD;
                    vbuf[n0 * VSTRIDE + oo] = y0;
                    vbuf[(n0 + 1) * VSTRIDE + oo] = y1;
                }
            }
        }
        __syncthreads();

        // ---------- Phase C: depthwise 5x5 conv + affine + exact GELU + residual ----------
        for (int t = tid; t < KD * NPIX; t += 256) {
            int c = t / NPIX;
            int p = t - c * NPIX;
            int py = p / RESX, px = p - py * RESX;
            float s = 0.f;
            #pragma unroll
            for (int dy = 0; dy < 5; dy++) {
                int yy = py + dy - 2;
                if (yy < 0 || yy >= RESX) continue;
                #pragma unroll
                for (int dx = 0; dx < 5; dx++) {
                    int xx = px + dx - 2;
                    if (xx < 0 || xx >= RESX) continue;
                    s += dww[c * 25 + dy * 5 + dx] * qbuf[c * NPIX + yy * RESX + xx];
                }
            }
            float dq = s * dsc[c] + dbi[c];
            float g = 0.5f * dq * (1.0f + erff(dq * 0.70710678118654752440f));
            qgbuf[t] = g + qbuf[t];
        }
        __syncthreads();

        // ---------- Phase D: attention ----------
        const ull* a2row = a2 + warp * 4 * NPIX;
        for (int rb = warp; rb < 49; rb += 8) {
            int n0 = rb * 4;
            ull qgr2[KD][2];
            #pragma unroll
            for (int c = 0; c < KD; c++) {
                const float* qr = &qgbuf[c * NPIX + n0];
                qgr2[c][0] = pk2(qr[0], qr[1]);
                qgr2[c][1] = pk2(qr[2], qr[3]);
            }
            float sv[4][7];
            #pragma unroll
            for (int j = 0; j < 7; j++) {
                int m = lane + 32 * j;
                if (m < NPIX) {
                    ull t0 = 0, t1 = 0;
                    #pragma unroll
                    for (int c = 0; c < KD; c++) {
                        float kk = kbuf[c * NPIX + m];
                        ull kd = pk2(kk, kk);
                        fma2(t0, qgr2[c][0], kd);
                        fma2(t1, qgr2[c][1], kd);
                    }
                    float s00, s01, s10, s11;
                    unpk2(t0, s00, s01);
                    unpk2(t1, s10, s11);
                    sv[0][j] = s00 * 0.25f + abh[bias_idxs[(n0 + 0) * NPIX + m]];
                    sv[1][j] = s01 * 0.25f + abh[bias_idxs[(n0 + 1) * NPIX + m]];
                    sv[2][j] = s10 * 0.25f + abh[bias_idxs[(n0 + 2) * NPIX + m]];
                    sv[3][j] = s11 * 0.25f + abh[bias_idxs[(n0 + 3) * NPIX + m]];
                } else {
                    sv[0][j] = -1e30f; sv[1][j] = -1e30f;
                    sv[2][j] = -1e30f; sv[3][j] = -1e30f;
                }
            }
            #pragma unroll
            for (int r = 0; r < 4; r++) {
                float mx = -1e30f;
                #pragma unroll
                for (int j = 0; j < 7; j++) mx = fmaxf(mx, sv[r][j]);
                #pragma unroll
                for (int off = 16; off; off >>= 1)
                    mx = fmaxf(mx, __shfl_xor_sync(0xffffffffu, mx, off));
                float sum = 0.f;
                #pragma unroll
                for (int j = 0; j < 7; j++) {
                    float e = expf(sv[r][j] - mx);
                    sv[r][j] = e;
                    sum += e;
                }
                #pragma unroll
                for (int off = 16; off; off >>= 1)
                    sum += __shfl_xor_sync(0xffffffffu, sum, off);
                float inv = 1.0f / sum;
                #pragma unroll
                for (int j = 0; j < 7; j++) {
                    int m = lane + 32 * j;
                    if (m < NPIX) {
                        float p = sv[r][j] * inv;
                        a2[(warp * 4 + r) * NPIX + m] = pk2(p, p);
                    }
                }
            }
            __syncwarp();
            ull acc[4] = {0, 0, 0, 0};
            #pragma unroll 4
            for (int m = 0; m < NPIX; m++) {
                ull vp = *(const ull*)&vbuf[m * VSTRIDE + 2 * lane];
                #pragma unroll
                for (int r = 0; r < 4; r++)
                    fma2(acc[r], a2row[r * NPIX + m], vp);
            }
            #pragma unroll
            for (int r = 0; r < 4; r++) {
                float o0, o1;
                unpk2(acc[r], o0, o1);
                int n = n0 + r;
                feat[(2 * lane) * NPIX + n] = o0;
                feat[(2 * lane + 1) * NPIX + n] = o1;
            }
            __syncwarp();
        }
        __syncthreads();

        // ---------- export relu(feat) -> g_cat_t, pixel-major, tf32-rounded ----------
        {
            float* gc = g_cat_t + ((size_t)b * NPIX) * DIM + i * DD;
            for (int idx = tid; idx < DD * NPIX; idx += 256) {
                int n = idx >> 6;          // pixel
                int d = idx & 63;          // channel within head
                float v = fmaxf(feat[d * NPIX + n], 0.f);
                gc[(size_t)n * DIM + d] = to_tf32(v);
            }
        }
        __syncthreads();
    }
}

// ---------------- prep: round proj_w to tf32 ----------------
__global__ void wprep_kernel(const float* __restrict__ proj_w) {
    int idx = blockIdx.x * 256 + threadIdx.x;
    g_wt[idx] = to_tf32(proj_w[idx]);
}

// ---------------- proj kernel: mma.sync tf32 GEMM ----------------
// out[o, n] = W[256,256] @ cat[n][k], N = 512*196 = 100352 pixels.
// CTA tile: M=256 x N=128; warp tile 64x64 (warps: 4 in M x 2 in N).
// K staged in chunks of 32 floats, double-buffered via cp.async.
#define PJ_NT 128
#define PJ_AS 36                    // smem row stride (floats), conflict-free frag loads
#define PJ_A_FLOATS (256 * PJ_AS)   // 9216
#define PJ_B_FLOATS (128 * PJ_AS)   // 4608
#define PJ_BUF_FLOATS (PJ_A_FLOATS + PJ_B_FLOATS)     // 13824
#define PJ_SMEM_BYTES (2 * PJ_BUF_FLOATS * 4)         // 110592

__global__ void __launch_bounds__(256, 1)
proj_mma_kernel(const float* __restrict__ proj_scale,
                const float* __restrict__ proj_bias,
                float* __restrict__ out)
{
    extern __shared__ float smf[];
    const uint32_t smem_base = smem_u32(smf);

    const int tid  = threadIdx.x;
    const int wid  = tid >> 5;
    const int lane = tid & 31;
    const int g    = lane >> 2;   // group id
    const int tig  = lane & 3;    // thread in group
    const int n0   = blockIdx.x * PJ_NT;

    const int o0 = (wid & 3) * 64;      // warp M offset
    const int nb = (wid >> 2) * 64;     // warp N offset

    float acc[4][8][4];
    #pragma unroll
    for (int mi = 0; mi < 4; mi++)
        #pragma unroll
        for (int ni = 0; ni < 8; ni++)
            #pragma unroll
            for (int c = 0; c < 4; c++) acc[mi][ni][c] = 0.f;

    // ---- chunk staging (cp.async) ----
    auto issue_chunk = [&](int c) {
        const int buf = c & 1;
        const int k0 = c * 32;
        const uint32_t abase = smem_base + (uint32_t)(buf * PJ_BUF_FLOATS) * 4u;
        const uint32_t bbase = abase + (uint32_t)PJ_A_FLOATS * 4u;
        // A: 256 rows x 8 float4
        #pragma unroll
        for (int it = 0; it < 8; it++) {
            int idx = it * 256 + tid;          // 0..2047
            int row = idx >> 3, k4 = idx & 7;
            CP_ASYNC16(abase + (uint32_t)(row * PJ_AS + k4 * 4) * 4u,
                       g_wt + (size_t)row * 256 + k0 + k4 * 4);
        }
        // B: 128 rows x 8 float4
        #pragma unroll
        for (int it = 0; it < 4; it++) {
            int idx = it * 256 + tid;          // 0..1023
            int row = idx >> 3, k4 = idx & 7;
            CP_ASYNC16(bbase + (uint32_t)(row * PJ_AS + k4 * 4) * 4u,
                       g_cat_t + (size_t)(n0 + row) * 256 + k0 + k4 * 4);
        }
        CP_COMMIT();
    };

    issue_chunk(0);

    for (int c = 0; c < 8; c++) {
        CP_WAIT0();
        __syncthreads();
        if (c < 7) issue_chunk(c + 1);

        const int buf = c & 1;
        const uint32_t* Asu = (const uint32_t*)(smf + buf * PJ_BUF_FLOATS);
        const uint32_t* Bsu = Asu + PJ_A_FLOATS;
        const int a_base = (o0 + g) * PJ_AS + tig;
        const int b_base = (nb + g) * PJ_AS + tig;

        #pragma unroll
        for (int k8 = 0; k8 < 32; k8 += 8) {
            uint32_t a[4][4];
            #pragma unroll
            for (int mi = 0; mi < 4; mi++) {
                int ab = a_base + mi * (16 * PJ_AS) + k8;
                a[mi][0] = Asu[ab];
                a[mi][1] = Asu[ab + 8 * PJ_AS];
                a[mi][2] = Asu[ab + 4];
                a[mi][3] = Asu[ab + 8 * PJ_AS + 4];
            }
            uint32_t bfr[8][2];
            #pragma unroll
            for (int ni = 0; ni < 8; ni++) {
                int bb = b_base + ni * (8 * PJ_AS) + k8;
                bfr[ni][0] = Bsu[bb];
                bfr[ni][1] = Bsu[bb + 4];
            }
            #pragma unroll
            for (int mi = 0; mi < 4; mi++)
                #pragma unroll
                for (int ni = 0; ni < 8; ni++)
                    mma_tf32(acc[mi][ni], a[mi], bfr[ni]);
        }
        __syncthreads();
    }

    // ---- epilogue: two N-halves through smem (stride 68), coalesced stores ----
    float* Ssm = smf;   // reuse buffers
    #pragma unroll
    for (int h = 0; h < 2; h++) {
        __syncthreads();
        if ((wid >> 2) == h) {
            #pragma unroll
            for (int mi = 0; mi < 4; mi++) {
                int orow = o0 + mi * 16 + g;
                #pragma unroll
                for (int ni = 0; ni < 8; ni++) {
                    int nl = ni * 8 + 2 * tig;
                    *(float2*)&Ssm[orow * 68 + nl] =
                        make_float2(acc[mi][ni][0], acc[mi][ni][1]);
                    *(float2*)&Ssm[(orow + 8) * 68 + nl] =
                        make_float2(acc[mi][ni][2], acc[mi][ni][3]);
                }
            }
        }
        __syncthreads();
        #pragma unroll 4
        for (int it = 0; it < 64; it++) {
            int idx = it * 256 + tid;
            int o = idx >> 6, nn = idx & 63;
            float v = Ssm[o * 68 + nn];
            v = v * proj_scale[o] + proj_bias[o];
            unsigned ng = (unsigned)(n0 + h * 64 + nn);
            unsigned bb = ng / 196u;
            unsigned pp = ng - bb * 196u;
            out[(size_t)bb * (DIM * NPIX) + (size_t)o * NPIX + pp] = v;
        }
    }
}

extern "C" void kernel_launch(void* const* d_in, const int* in_sizes, int n_in,
                              void* d_out, int out_size)
{
    (void)in_sizes; (void)n_in; (void)out_size;
    const float* x          = (const float*)d_in[0];
    const float* qkv_w      = (const float*)d_in[1];
    const float* qkv_scale  = (const float*)d_in[2];
    const float* qkv_bias   = (const float*)d_in[3];
    const float* dw_w       = (const float*)d_in[4];
    const float* dw_scale   = (const float*)d_in[5];
    const float* dw_bias    = (const float*)d_in[6];
    const float* proj_w     = (const float*)d_in[7];
    const float* proj_scale = (const float*)d_in[8];
    const float* proj_bias  = (const float*)d_in[9];
    const float* attn_b     = (const float*)d_in[10];
    const int*   bias_idxs  = (const int*)d_in[11];
    float* out = (float*)d_out;

    cudaFuncSetAttribute(cascade_kernel, cudaFuncAttributeMaxDynamicSharedMemorySize, SMEM1_BYTES);
    cudaFuncSetAttribute(proj_mma_kernel, cudaFuncAttributeMaxDynamicSharedMemorySize, PJ_SMEM_BYTES);

    wprep_kernel<<<DIM * DIM / 256, 256>>>(proj_w);
    cascade_kernel<<<BATCH, 256, SMEM1_BYTES>>>(x, qkv_w, qkv_scale, qkv_bias,
                                                dw_w, dw_scale, dw_bias,
                                                attn_b, bias_idxs);
    proj_mma_kernel<<<(BATCH * NPIX) / PJ_NT, 256, PJ_SMEM_BYTES>>>(proj_scale, proj_bias, out);
}

// round 4
// speedup vs baseline: 1.8030x; 1.3861x over previous
#include <cuda_runtime.h>
#include <math.h>
#include <cstdint>

// ---------------- problem constants ----------------
#define BATCH 512
#define NH 4
#define KD 16
#define DD 64
#define DIM 256
#define QO 96
#define RESX 14
#define NPIX 196

typedef unsigned long long ull;

// global scratch: relu'd concat of head outputs, PIXEL-MAJOR [b*196+n][c], tf32-rounded
__device__ __align__(128) float g_cat_t[(size_t)BATCH * NPIX * DIM];
// tf32-rounded proj weights
__device__ __align__(128) float g_wt[DIM * DIM];

__device__ __forceinline__ float to_tf32(float x) {
    float r; asm("cvt.rna.satfinite.tf32.f32 %0, %1;" : "=f"(r) : "f"(x)); return r;
}
__device__ __forceinline__ uint32_t smem_u32(const void* p) {
    uint32_t a;
    asm("{ .reg .u64 t; cvta.to.shared.u64 t, %1; cvt.u32.u64 %0, t; }" : "=r"(a) : "l"(p));
    return a;
}

// ---------------- cp.async helpers ----------------
#define CP_ASYNC16(dst_u32, src_ptr) \
    asm volatile("cp.async.cg.shared.global [%0], [%1], 16;" :: "r"(dst_u32), "l"(src_ptr))
#define CP_COMMIT() asm volatile("cp.async.commit_group;" ::: "memory")
#define CP_WAIT0()  asm volatile("cp.async.wait_group 0;" ::: "memory")

// ---------------- mma.sync tf32 m16n8k8 ----------------
__device__ __forceinline__ void mma_tf32(float* d, const uint32_t* a, const uint32_t* b) {
    asm volatile(
        "mma.sync.aligned.m16n8k8.row.col.f32.tf32.tf32.f32 "
        "{%0,%1,%2,%3}, {%4,%5,%6,%7}, {%8,%9}, {%0,%1,%2,%3};"
        : "+f"(d[0]), "+f"(d[1]), "+f"(d[2]), "+f"(d[3])
        : "r"(a[0]), "r"(a[1]), "r"(a[2]), "r"(a[3]), "r"(b[0]), "r"(b[1]));
}
__device__ __forceinline__ void mma8(float* d, float a0, float a1, float a2, float a3,
                                     float b0, float b1) {
    uint32_t A[4] = {__float_as_uint(a0), __float_as_uint(a1),
                     __float_as_uint(a2), __float_as_uint(a3)};
    uint32_t B[2] = {__float_as_uint(b0), __float_as_uint(b1)};
    mma_tf32(d, A, B);
}

// ---------------- cascade smem layout (float offsets) ----------------
// featT [200][68]   rows n (196..199 zero), cols c
// wq    [96][68]
// qT    [224][18]   fp32 q (for conv)
// kT    [224][18]   tf32
// qgT   [224][18]   tf32, rows 196..223 MUST stay zero
// v     [64][204]   tf32, [d][m]
// S/p   [32][204]
#define CF_FEAT 0
#define CF_WQ   13600
#define CF_QT   20128
#define CF_KT   24160
#define CF_QG   28192
#define CF_V    32224
#define CF_S    45280
#define CF_ABH  51808
#define CF_QSC  52004
#define CF_QBI  52100
#define CF_DSC  52196
#define CF_DBI  52212
#define CF_DWW  52228
#define CF_END  52628
#define SMEM1_BYTES (CF_END * 4)      // 210512

__global__ void __launch_bounds__(256, 1)
cascade_kernel(const float* __restrict__ x,
               const float* __restrict__ qkv_w,
               const float* __restrict__ qkv_scale,
               const float* __restrict__ qkv_bias,
               const float* __restrict__ dw_w,
               const float* __restrict__ dw_scale,
               const float* __restrict__ dw_bias,
               const float* __restrict__ attention_biases,
               const int*   __restrict__ bias_idxs)
{
    extern __shared__ float sm[];
    float* featT = sm + CF_FEAT;
    float* wq    = sm + CF_WQ;
    float* qT    = sm + CF_QT;
    float* kT    = sm + CF_KT;
    float* qgT   = sm + CF_QG;
    float* vv    = sm + CF_V;
    float* S     = sm + CF_S;
    float* abh   = sm + CF_ABH;
    float* qsc   = sm + CF_QSC;
    float* qbi   = sm + CF_QBI;
    float* dsc   = sm + CF_DSC;
    float* dbi   = sm + CF_DBI;
    float* dww   = sm + CF_DWW;

    const int b    = blockIdx.x;
    const int tid  = threadIdx.x;
    const int warp = tid >> 5;
    const int lane = tid & 31;
    const int g    = lane >> 2;   // group id (0..7)
    const int tig  = lane & 3;    // thread in group (0..3)

    // one-time zero padding
    for (int idx = tid; idx < 28 * 18; idx += 256) qgT[196 * 18 + idx] = 0.f;
    for (int idx = tid; idx < 4 * 68; idx += 256)  featT[196 * 68 + idx] = 0.f;
    __syncthreads();

    for (int i = 0; i < NH; i++) {
        // ---------- Phase A: feat accumulate (tf32-rounded) + weight staging ----------
        {
            const float* xb = x + ((size_t)b * DIM + i * DD) * NPIX;
            if (i == 0) {
                for (int idx = tid; idx < DD * NPIX; idx += 256) {
                    int c = idx / NPIX, n = idx - c * NPIX;
                    featT[n * 68 + c] = to_tf32(xb[idx]);
                }
            } else {
                for (int idx = tid; idx < DD * NPIX; idx += 256) {
                    int c = idx / NPIX, n = idx - c * NPIX;
                    featT[n * 68 + c] = to_tf32(featT[n * 68 + c] + xb[idx]);
                }
            }
            for (int idx = tid; idx < QO * 64; idx += 256)
                wq[(idx >> 6) * 68 + (idx & 63)] = to_tf32(qkv_w[i * QO * 64 + idx]);
            for (int idx = tid; idx < 400; idx += 256) dww[idx] = dw_w[i * 400 + idx];
            if (tid < NPIX) abh[tid] = attention_biases[i * NPIX + tid];
            if (tid < QO) { qsc[tid] = qkv_scale[i * QO + tid]; qbi[tid] = qkv_bias[i * QO + tid]; }
            if (tid < KD) { dsc[tid] = dw_scale[i * KD + tid]; dbi[tid] = dw_bias[i * KD + tid]; }
        }
        __syncthreads();

        // ---------- Phase B: QKV via mma (M=96 o, N=200 n, K=64 c) ----------
        for (int nt = warp; nt < 25; nt += 8) {
            const int nb0 = nt * 8;
            float B0[8], B1[8];
            #pragma unroll
            for (int ks = 0; ks < 8; ks++) {
                B0[ks] = featT[(nb0 + g) * 68 + ks * 8 + tig];
                B1[ks] = featT[(nb0 + g) * 68 + ks * 8 + tig + 4];
            }
            #pragma unroll
            for (int mt = 0; mt < 6; mt++) {
                const int o0 = mt * 16;
                float dd[4] = {0.f, 0.f, 0.f, 0.f};
                #pragma unroll
                for (int ks = 0; ks < 8; ks++) {
                    float a0 = wq[(o0 + g) * 68 + ks * 8 + tig];
                    float a1 = wq[(o0 + g + 8) * 68 + ks * 8 + tig];
                    float a2 = wq[(o0 + g) * 68 + ks * 8 + tig + 4];
                    float a3 = wq[(o0 + g + 8) * 68 + ks * 8 + tig + 4];
                    mma8(dd, a0, a1, a2, a3, B0[ks], B1[ks]);
                }
                const int oA = o0 + g, oB = oA + 8;
                const float sA = qsc[oA], bA = qbi[oA];
                const float sB = qsc[oB], bB = qbi[oB];
                float y0 = dd[0] * sA + bA, y1 = dd[1] * sA + bA;
                float y2 = dd[2] * sB + bB, y3 = dd[3] * sB + bB;
                const int nc = nb0 + 2 * tig;
                if (mt == 0) {
                    qT[nc * 18 + oA] = y0; qT[(nc + 1) * 18 + oA] = y1;
                    qT[nc * 18 + oB] = y2; qT[(nc + 1) * 18 + oB] = y3;
                } else if (mt == 1) {
                    int c0 = oA - 16, c1 = oB - 16;
                    kT[nc * 18 + c0] = to_tf32(y0); kT[(nc + 1) * 18 + c0] = to_tf32(y1);
                    kT[nc * 18 + c1] = to_tf32(y2); kT[(nc + 1) * 18 + c1] = to_tf32(y3);
                } else {
                    int dA = oA - 32, dB = oB - 32;
                    vv[dA * 204 + nc] = to_tf32(y0); vv[dA * 204 + nc + 1] = to_tf32(y1);
                    vv[dB * 204 + nc] = to_tf32(y2); vv[dB * 204 + nc + 1] = to_tf32(y3);
                }
            }
        }
        __syncthreads();

        // ---------- Phase C: depthwise 5x5 conv + affine + exact GELU + residual ----------
        for (int t = tid; t < KD * NPIX; t += 256) {
            int n = t >> 4, c = t & 15;
            int py = n / RESX, px = n - py * RESX;
            float s = 0.f;
            #pragma unroll
            for (int dy = 0; dy < 5; dy++) {
                int yy = py + dy - 2;
                if (yy < 0 || yy >= RESX) continue;
                #pragma unroll
                for (int dx = 0; dx < 5; dx++) {
                    int xx = px + dx - 2;
                    if (xx < 0 || xx >= RESX) continue;
                    s += dww[c * 25 + dy * 5 + dx] * qT[(yy * RESX + xx) * 18 + c];
                }
            }
            float dq = s * dsc[c] + dbi[c];
            float gl = 0.5f * dq * (1.0f + erff(dq * 0.70710678118654752440f));
            qgT[n * 18 + c] = to_tf32(gl + qT[n * 18 + c]);
        }
        __syncthreads();

        // ---------- Phase D: attention in 7 tiles of 32 rows ----------
        for (int t32 = 0; t32 < 7; t32++) {
            const int r0 = t32 * 32;

            // D1: QK  S[n][m] = qg[n]·k[m] * 0.25 + bias
            for (int nt = warp; nt < 25; nt += 8) {
                const int mm0 = nt * 8;
                float b00 = kT[(mm0 + g) * 18 + tig],     b01 = kT[(mm0 + g) * 18 + tig + 4];
                float b10 = kT[(mm0 + g) * 18 + tig + 8], b11 = kT[(mm0 + g) * 18 + tig + 12];
                #pragma unroll
                for (int mt = 0; mt < 2; mt++) {
                    const int rr = r0 + mt * 16;
                    float dd[4] = {0.f, 0.f, 0.f, 0.f};
                    mma8(dd, qgT[(rr + g) * 18 + tig],     qgT[(rr + g + 8) * 18 + tig],
                             qgT[(rr + g) * 18 + tig + 4], qgT[(rr + g + 8) * 18 + tig + 4],
                             b00, b01);
                    mma8(dd, qgT[(rr + g) * 18 + tig + 8],  qgT[(rr + g + 8) * 18 + tig + 8],
                             qgT[(rr + g) * 18 + tig + 12], qgT[(rr + g + 8) * 18 + tig + 12],
                             b10, b11);
                    const int nlA = mt * 16 + g, nlB = nlA + 8;
                    const int ngA = min(r0 + nlA, 195), ngB = min(r0 + nlB, 195);
                    const int m0 = mm0 + 2 * tig;
                    const int mc0 = min(m0, 195), mc1 = min(m0 + 1, 195);
                    float s00 = dd[0] * 0.25f + abh[bias_idxs[ngA * NPIX + mc0]];
                    float s01 = dd[1] * 0.25f + abh[bias_idxs[ngA * NPIX + mc1]];
                    float s10 = dd[2] * 0.25f + abh[bias_idxs[ngB * NPIX + mc0]];
                    float s11 = dd[3] * 0.25f + abh[bias_idxs[ngB * NPIX + mc1]];
                    S[nlA * 204 + m0] = s00; S[nlA * 204 + m0 + 1] = s01;
                    S[nlB * 204 + m0] = s10; S[nlB * 204 + m0 + 1] = s11;
                }
            }
            __syncthreads();

            // D2: softmax rows (4 per warp), in place; zero pad cols for AV
            #pragma unroll
            for (int rr = 0; rr < 4; rr++) {
                const int r = warp * 4 + rr;
                float e[7];
                float mx = -1e30f;
                #pragma unroll
                for (int j = 0; j < 7; j++) {
                    int m = lane + 32 * j;
                    float vva = (m < NPIX) ? S[r * 204 + m] : -1e30f;
                    e[j] = vva;
                    mx = fmaxf(mx, vva);
                }
                #pragma unroll
                for (int off = 16; off; off >>= 1)
                    mx = fmaxf(mx, __shfl_xor_sync(0xffffffffu, mx, off));
                float sum = 0.f;
                #pragma unroll
                for (int j = 0; j < 7; j++) { e[j] = __expf(e[j] - mx); sum += e[j]; }
                #pragma unroll
                for (int off = 16; off; off >>= 1)
                    sum += __shfl_xor_sync(0xffffffffu, sum, off);
                float inv = 1.0f / sum;
                #pragma unroll
                for (int j = 0; j < 7; j++) {
                    int m = lane + 32 * j;
                    if (m < NPIX) S[r * 204 + m] = to_tf32(e[j] * inv);
                }
                if (lane < 8) S[r * 204 + 196 + lane] = 0.f;
            }
            __syncthreads();

            // D3: AV  out[n][d] = sum_m p[n][m] v[d][m]; each warp owns d-block = warp*8
            {
                const int d0c = warp * 8;
                float dd0[4] = {0.f, 0.f, 0.f, 0.f};
                float dd1[4] = {0.f, 0.f, 0.f, 0.f};
                #pragma unroll
                for (int ks = 0; ks < 25; ks++) {
                    const int k0 = ks * 8 + tig;
                    float b0 = vv[(d0c + g) * 204 + k0];
                    float b1 = vv[(d0c + g) * 204 + k0 + 4];
                    mma8(dd0, S[g * 204 + k0],      S[(g + 8) * 204 + k0],
                              S[g * 204 + k0 + 4],  S[(g + 8) * 204 + k0 + 4], b0, b1);
                    mma8(dd1, S[(16 + g) * 204 + k0],     S[(24 + g) * 204 + k0],
                              S[(16 + g) * 204 + k0 + 4], S[(24 + g) * 204 + k0 + 4], b0, b1);
                }
                const int dc = d0c + 2 * tig;
                float* gcb = g_cat_t + ((size_t)b * NPIX) * DIM + i * DD;
                #pragma unroll
                for (int half = 0; half < 2; half++) {
                    float* dd = half ? dd1 : dd0;
                    int nA = r0 + half * 16 + g;
                    int nB = nA + 8;
                    if (nA < NPIX) {
                        featT[nA * 68 + dc] = dd[0];
                        featT[nA * 68 + dc + 1] = dd[1];
                        float2 rl = make_float2(to_tf32(fmaxf(dd[0], 0.f)),
                                                to_tf32(fmaxf(dd[1], 0.f)));
                        *(float2*)&gcb[(size_t)nA * DIM + dc] = rl;
                    }
                    if (nB < NPIX) {
                        featT[nB * 68 + dc] = dd[2];
                        featT[nB * 68 + dc + 1] = dd[3];
                        float2 rl = make_float2(to_tf32(fmaxf(dd[2], 0.f)),
                                                to_tf32(fmaxf(dd[3], 0.f)));
                        *(float2*)&gcb[(size_t)nB * DIM + dc] = rl;
                    }
                }
            }
            __syncthreads();
        }
    }
}

// ---------------- prep: round proj_w to tf32 ----------------
__global__ void wprep_kernel(const float* __restrict__ proj_w) {
    int idx = blockIdx.x * 256 + threadIdx.x;
    g_wt[idx] = to_tf32(proj_w[idx]);
}

// ---------------- proj kernel: mma.sync tf32 GEMM (unchanged from R3) ----------------
#define PJ_NT 128
#define PJ_AS 36
#define PJ_A_FLOATS (256 * PJ_AS)
#define PJ_B_FLOATS (128 * PJ_AS)
#define PJ_BUF_FLOATS (PJ_A_FLOATS + PJ_B_FLOATS)
#define PJ_SMEM_BYTES (2 * PJ_BUF_FLOATS * 4)

__global__ void __launch_bounds__(256, 1)
proj_mma_kernel(const float* __restrict__ proj_scale,
                const float* __restrict__ proj_bias,
                float* __restrict__ out)
{
    extern __shared__ float smf[];
    const uint32_t smem_base = smem_u32(smf);

    const int tid  = threadIdx.x;
    const int wid  = tid >> 5;
    const int lane = tid & 31;
    const int g    = lane >> 2;
    const int tig  = lane & 3;
    const int n0   = blockIdx.x * PJ_NT;

    const int o0 = (wid & 3) * 64;
    const int nb = (wid >> 2) * 64;

    float acc[4][8][4];
    #pragma unroll
    for (int mi = 0; mi < 4; mi++)
        #pragma unroll
        for (int ni = 0; ni < 8; ni++)
            #pragma unroll
            for (int c = 0; c < 4; c++) acc[mi][ni][c] = 0.f;

    auto issue_chunk = [&](int c) {
        const int buf = c & 1;
        const int k0 = c * 32;
        const uint32_t abase = smem_base + (uint32_t)(buf * PJ_BUF_FLOATS) * 4u;
        const uint32_t bbase = abase + (uint32_t)PJ_A_FLOATS * 4u;
        #pragma unroll
        for (int it = 0; it < 8; it++) {
            int idx = it * 256 + tid;
            int row = idx >> 3, k4 = idx & 7;
            CP_ASYNC16(abase + (uint32_t)(row * PJ_AS + k4 * 4) * 4u,
                       g_wt + (size_t)row * 256 + k0 + k4 * 4);
        }
        #pragma unroll
        for (int it = 0; it < 4; it++) {
            int idx = it * 256 + tid;
            int row = idx >> 3, k4 = idx & 7;
            CP_ASYNC16(bbase + (uint32_t)(row * PJ_AS + k4 * 4) * 4u,
                       g_cat_t + (size_t)(n0 + row) * 256 + k0 + k4 * 4);
        }
        CP_COMMIT();
    };

    issue_chunk(0);

    for (int c = 0; c < 8; c++) {
        CP_WAIT0();
        __syncthreads();
        if (c < 7) issue_chunk(c + 1);

        const int buf = c & 1;
        const uint32_t* Asu = (const uint32_t*)(smf + buf * PJ_BUF_FLOATS);
        const uint32_t* Bsu = Asu + PJ_A_FLOATS;
        const int a_base = (o0 + g) * PJ_AS + tig;
        const int b_base = (nb + g) * PJ_AS + tig;

        #pragma unroll
        for (int k8 = 0; k8 < 32; k8 += 8) {
            uint32_t a[4][4];
            #pragma unroll
            for (int mi = 0; mi < 4; mi++) {
                int ab = a_base + mi * (16 * PJ_AS) + k8;
                a[mi][0] = Asu[ab];
                a[mi][1] = Asu[ab + 8 * PJ_AS];
                a[mi][2] = Asu[ab + 4];
                a[mi][3] = Asu[ab + 8 * PJ_AS + 4];
            }
            uint32_t bfr[8][2];
            #pragma unroll
            for (int ni = 0; ni < 8; ni++) {
                int bb = b_base + ni * (8 * PJ_AS) + k8;
                bfr[ni][0] = Bsu[bb];
                bfr[ni][1] = Bsu[bb + 4];
            }
            #pragma unroll
            for (int mi = 0; mi < 4; mi++)
                #pragma unroll
                for (int ni = 0; ni < 8; ni++)
                    mma_tf32(acc[mi][ni], a[mi], bfr[ni]);
        }
        __syncthreads();
    }

    float* Ssm = smf;
    #pragma unroll
    for (int h = 0; h < 2; h++) {
        __syncthreads();
        if ((wid >> 2) == h) {
            #pragma unroll
            for (int mi = 0; mi < 4; mi++) {
                int orow = o0 + mi * 16 + g;
                #pragma unroll
                for (int ni = 0; ni < 8; ni++) {
                    int nl = ni * 8 + 2 * tig;
                    *(float2*)&Ssm[orow * 68 + nl] =
                        make_float2(acc[mi][ni][0], acc[mi][ni][1]);
                    *(float2*)&Ssm[(orow + 8) * 68 + nl] =
                        make_float2(acc[mi][ni][2], acc[mi][ni][3]);
                }
            }
        }
        __syncthreads();
        #pragma unroll 4
        for (int it = 0; it < 64; it++) {
            int idx = it * 256 + tid;
            int o = idx >> 6, nn = idx & 63;
            float v = Ssm[o * 68 + nn];
            v = v * proj_scale[o] + proj_bias[o];
            unsigned ng = (unsigned)(n0 + h * 64 + nn);
            unsigned bb = ng / 196u;
            unsigned pp = ng - bb * 196u;
            out[(size_t)bb * (DIM * NPIX) + (size_t)o * NPIX + pp] = v;
        }
    }
}

extern "C" void kernel_launch(void* const* d_in, const int* in_sizes, int n_in,
                              void* d_out, int out_size)
{
    (void)in_sizes; (void)n_in; (void)out_size;
    const float* x          = (const float*)d_in[0];
    const float* qkv_w      = (const float*)d_in[1];
    const float* qkv_scale  = (const float*)d_in[2];
    const float* qkv_bias   = (const float*)d_in[3];
    const float* dw_w       = (const float*)d_in[4];
    const float* dw_scale   = (const float*)d_in[5];
    const float* dw_bias    = (const float*)d_in[6];
    const float* proj_w     = (const float*)d_in[7];
    const float* proj_scale = (const float*)d_in[8];
    const float* proj_bias  = (const float*)d_in[9];
    const float* attn_b     = (const float*)d_in[10];
    const int*   bias_idxs  = (const int*)d_in[11];
    float* out = (float*)d_out;

    cudaFuncSetAttribute(cascade_kernel, cudaFuncAttributeMaxDynamicSharedMemorySize, SMEM1_BYTES);
    cudaFuncSetAttribute(proj_mma_kernel, cudaFuncAttributeMaxDynamicSharedMemorySize, PJ_SMEM_BYTES);

    wprep_kernel<<<DIM * DIM / 256, 256>>>(proj_w);
    cascade_kernel<<<BATCH, 256, SMEM1_BYTES>>>(x, qkv_w, qkv_scale, qkv_bias,
                                                dw_w, dw_scale, dw_bias,
                                                attn_b, bias_idxs);
    proj_mma_kernel<<<(BATCH * NPIX) / PJ_NT, 256, PJ_SMEM_BYTES>>>(proj_scale, proj_bias, out);
}

// round 5
// speedup vs baseline: 2.2533x; 1.2498x over previous
#include <cuda_runtime.h>
#include <math.h>
#include <cstdint>

// ---------------- problem constants ----------------
#define BATCH 512
#define NH 4
#define KD 16
#define DD 64
#define DIM 256
#define QO 96
#define RESX 14
#define NPIX 196

typedef unsigned long long ull;

// global scratch: relu'd concat of head outputs, PIXEL-MAJOR [b*196+n][c], tf32-rounded
__device__ __align__(128) float g_cat_t[(size_t)BATCH * NPIX * DIM];
// tf32-rounded proj weights
__device__ __align__(128) float g_wt[DIM * DIM];
// pre-gathered attention bias matrices [h][n][m] (+pad for tail overrun reads)
__device__ __align__(128) float g_abmat[NH * NPIX * NPIX + 16];

__device__ __forceinline__ float to_tf32(float x) {
    float r; asm("cvt.rna.satfinite.tf32.f32 %0, %1;" : "=f"(r) : "f"(x)); return r;
}
__device__ __forceinline__ uint32_t smem_u32(const void* p) {
    uint32_t a;
    asm("{ .reg .u64 t; cvta.to.shared.u64 t, %1; cvt.u32.u64 %0, t; }" : "=r"(a) : "l"(p));
    return a;
}

// ---------------- cp.async helpers ----------------
#define CP_ASYNC16(dst_u32, src_ptr) \
    asm volatile("cp.async.cg.shared.global [%0], [%1], 16;" :: "r"(dst_u32), "l"(src_ptr))
#define CP_COMMIT() asm volatile("cp.async.commit_group;" ::: "memory")
#define CP_WAIT0()  asm volatile("cp.async.wait_group 0;" ::: "memory")

// ---------------- mma.sync tf32 m16n8k8 ----------------
__device__ __forceinline__ void mma_tf32(float* d, const uint32_t* a, const uint32_t* b) {
    asm volatile(
        "mma.sync.aligned.m16n8k8.row.col.f32.tf32.tf32.f32 "
        "{%0,%1,%2,%3}, {%4,%5,%6,%7}, {%8,%9}, {%0,%1,%2,%3};"
        : "+f"(d[0]), "+f"(d[1]), "+f"(d[2]), "+f"(d[3])
        : "r"(a[0]), "r"(a[1]), "r"(a[2]), "r"(a[3]), "r"(b[0]), "r"(b[1]));
}
__device__ __forceinline__ void mma8(float* d, float a0, float a1, float a2, float a3,
                                     float b0, float b1) {
    uint32_t A[4] = {__float_as_uint(a0), __float_as_uint(a1),
                     __float_as_uint(a2), __float_as_uint(a3)};
    uint32_t B[2] = {__float_as_uint(b0), __float_as_uint(b1)};
    mma_tf32(d, A, B);
}

// ---------------- cascade smem layout (float offsets) ----------------
#define CF_FEAT 0
#define CF_WQ   13600
#define CF_QT   20128
#define CF_KT   24160
#define CF_QG   28192
#define CF_V    32224
#define CF_S    45280
#define CF_QSC  52004
#define CF_QBI  52100
#define CF_DSC  52196
#define CF_DBI  52212
#define CF_DWW  52228
#define CF_END  52628
#define SMEM1_BYTES (CF_END * 4)      // 210512

__global__ void __launch_bounds__(512, 1)
cascade_kernel(const float* __restrict__ x,
               const float* __restrict__ qkv_w,
               const float* __restrict__ qkv_scale,
               const float* __restrict__ qkv_bias,
               const float* __restrict__ dw_w,
               const float* __restrict__ dw_scale,
               const float* __restrict__ dw_bias)
{
    extern __shared__ float sm[];
    float* featT = sm + CF_FEAT;
    float* wq    = sm + CF_WQ;
    float* qT    = sm + CF_QT;
    float* kT    = sm + CF_KT;
    float* qgT   = sm + CF_QG;
    float* vv    = sm + CF_V;
    float* S     = sm + CF_S;
    float* qsc   = sm + CF_QSC;
    float* qbi   = sm + CF_QBI;
    float* dsc   = sm + CF_DSC;
    float* dbi   = sm + CF_DBI;
    float* dww   = sm + CF_DWW;

    const int b    = blockIdx.x;
    const int tid  = threadIdx.x;
    const int warp = tid >> 5;    // 0..15
    const int lane = tid & 31;
    const int g    = lane >> 2;   // 0..7
    const int tig  = lane & 3;    // 0..3

    // one-time zero padding
    for (int idx = tid; idx < 28 * 18; idx += 512) qgT[196 * 18 + idx] = 0.f;
    for (int idx = tid; idx < 4 * 68; idx += 512)  featT[196 * 68 + idx] = 0.f;
    __syncthreads();

    for (int i = 0; i < NH; i++) {
        // ---------- Phase A: feat accumulate (tf32-rounded) + weight staging ----------
        {
            const float* xb = x + ((size_t)b * DIM + i * DD) * NPIX;
            if (i == 0) {
                for (int idx = tid; idx < DD * NPIX; idx += 512) {
                    int c = idx / NPIX, n = idx - c * NPIX;
                    featT[n * 68 + c] = to_tf32(xb[idx]);
                }
            } else {
                for (int idx = tid; idx < DD * NPIX; idx += 512) {
                    int c = idx / NPIX, n = idx - c * NPIX;
                    featT[n * 68 + c] = to_tf32(featT[n * 68 + c] + xb[idx]);
                }
            }
            for (int idx = tid; idx < QO * 64; idx += 512)
                wq[(idx >> 6) * 68 + (idx & 63)] = to_tf32(qkv_w[i * QO * 64 + idx]);
            if (tid < 400) dww[tid] = dw_w[i * 400 + tid];
            if (tid >= 416 && tid < 416 + QO) {
                int o = tid - 416;
                qsc[o] = qkv_scale[i * QO + o]; qbi[o] = qkv_bias[i * QO + o];
            }
            if (tid >= 480 && tid < 480 + KD) {
                int c = tid - 480;
                dsc[c] = dw_scale[i * KD + c]; dbi[c] = dw_bias[i * KD + c];
            }
        }
        __syncthreads();

        // ---------- Phase B: QKV via mma (M=96 o, N=200 n, K=64 c), 25 warp tasks ----------
        for (int nt = warp; nt < 25; nt += 16) {
            const int nb0 = nt * 8;
            float B0[8], B1[8];
            #pragma unroll
            for (int ks = 0; ks < 8; ks++) {
                B0[ks] = featT[(nb0 + g) * 68 + ks * 8 + tig];
                B1[ks] = featT[(nb0 + g) * 68 + ks * 8 + tig + 4];
            }
            #pragma unroll
            for (int mp = 0; mp < 3; mp++) {
                const int oX = (2 * mp) * 16, oY = (2 * mp + 1) * 16;
                float dd0[4] = {0.f, 0.f, 0.f, 0.f};
                float dd1[4] = {0.f, 0.f, 0.f, 0.f};
                #pragma unroll
                for (int ks = 0; ks < 8; ks++) {
                    mma8(dd0, wq[(oX + g) * 68 + ks * 8 + tig],
                              wq[(oX + g + 8) * 68 + ks * 8 + tig],
                              wq[(oX + g) * 68 + ks * 8 + tig + 4],
                              wq[(oX + g + 8) * 68 + ks * 8 + tig + 4],
                              B0[ks], B1[ks]);
                    mma8(dd1, wq[(oY + g) * 68 + ks * 8 + tig],
                              wq[(oY + g + 8) * 68 + ks * 8 + tig],
                              wq[(oY + g) * 68 + ks * 8 + tig + 4],
                              wq[(oY + g + 8) * 68 + ks * 8 + tig + 4],
                              B0[ks], B1[ks]);
                }
                #pragma unroll
                for (int h = 0; h < 2; h++) {
                    const int mt = 2 * mp + h;
                    float* dd = h ? dd1 : dd0;
                    const int oA = mt * 16 + g, oB = oA + 8;
                    const float sA = qsc[oA], bA = qbi[oA];
                    const float sB = qsc[oB], bB = qbi[oB];
                    float y0 = dd[0] * sA + bA, y1 = dd[1] * sA + bA;
                    float y2 = dd[2] * sB + bB, y3 = dd[3] * sB + bB;
                    const int nc = nb0 + 2 * tig;
                    if (mt == 0) {
                        qT[nc * 18 + oA] = y0; qT[(nc + 1) * 18 + oA] = y1;
                        qT[nc * 18 + oB] = y2; qT[(nc + 1) * 18 + oB] = y3;
                    } else if (mt == 1) {
                        int c0 = oA - 16, c1 = oB - 16;
                        kT[nc * 18 + c0] = to_tf32(y0); kT[(nc + 1) * 18 + c0] = to_tf32(y1);
                        kT[nc * 18 + c1] = to_tf32(y2); kT[(nc + 1) * 18 + c1] = to_tf32(y3);
                    } else {
                        int dA = oA - 32, dB = oB - 32;
                        *(float2*)&vv[dA * 204 + nc] = make_float2(to_tf32(y0), to_tf32(y1));
                        *(float2*)&vv[dB * 204 + nc] = make_float2(to_tf32(y2), to_tf32(y3));
                    }
                }
            }
        }
        __syncthreads();

        // ---------- Phase C: depthwise 5x5 conv + affine + exact GELU + residual ----------
        for (int t = tid; t < KD * NPIX; t += 512) {
            int n = t >> 4, c = t & 15;
            int py = n / RESX, px = n - py * RESX;
            float s = 0.f;
            #pragma unroll
            for (int dy = 0; dy < 5; dy++) {
                int yy = py + dy - 2;
                if (yy < 0 || yy >= RESX) continue;
                #pragma unroll
                for (int dx = 0; dx < 5; dx++) {
                    int xx = px + dx - 2;
                    if (xx < 0 || xx >= RESX) continue;
                    s += dww[c * 25 + dy * 5 + dx] * qT[(yy * RESX + xx) * 18 + c];
                }
            }
            float dq = s * dsc[c] + dbi[c];
            float gl = 0.5f * dq * (1.0f + erff(dq * 0.70710678118654752440f));
            qgT[n * 18 + c] = to_tf32(gl + qT[n * 18 + c]);
        }
        __syncthreads();

        const float* abm = g_abmat + (size_t)i * (NPIX * NPIX);

        // ---------- Phase D: attention in 7 tiles of 32 rows ----------
        for (int t32 = 0; t32 < 7; t32++) {
            const int r0 = t32 * 32;

            // D1: QK  S[n][m] = qg[n]·k[m] * 0.25 + bias
            for (int nt = warp; nt < 25; nt += 16) {
                const int mm0 = nt * 8;
                float b00 = kT[(mm0 + g) * 18 + tig],     b01 = kT[(mm0 + g) * 18 + tig + 4];
                float b10 = kT[(mm0 + g) * 18 + tig + 8], b11 = kT[(mm0 + g) * 18 + tig + 12];
                #pragma unroll
                for (int mt = 0; mt < 2; mt++) {
                    const int rr = r0 + mt * 16;
                    float dd[4] = {0.f, 0.f, 0.f, 0.f};
                    mma8(dd, qgT[(rr + g) * 18 + tig],     qgT[(rr + g + 8) * 18 + tig],
                             qgT[(rr + g) * 18 + tig + 4], qgT[(rr + g + 8) * 18 + tig + 4],
                             b00, b01);
                    mma8(dd, qgT[(rr + g) * 18 + tig + 8],  qgT[(rr + g + 8) * 18 + tig + 8],
                             qgT[(rr + g) * 18 + tig + 12], qgT[(rr + g + 8) * 18 + tig + 12],
                             b10, b11);
                    const int nlA = mt * 16 + g, nlB = nlA + 8;
                    const int ngA = min(r0 + nlA, 195), ngB = min(r0 + nlB, 195);
                    const int m0 = mm0 + 2 * tig;
                    float2 abA = *(const float2*)&abm[(size_t)ngA * NPIX + m0];
                    float2 abB = *(const float2*)&abm[(size_t)ngB * NPIX + m0];
                    S[nlA * 204 + m0]     = dd[0] * 0.25f + abA.x;
                    S[nlA * 204 + m0 + 1] = dd[1] * 0.25f + abA.y;
                    S[nlB * 204 + m0]     = dd[2] * 0.25f + abB.x;
                    S[nlB * 204 + m0 + 1] = dd[3] * 0.25f + abB.y;
                }
            }
            __syncthreads();

            // D2: softmax rows (2 per warp), in place; zero pad cols
            #pragma unroll
            for (int rr = 0; rr < 2; rr++) {
                const int r = warp * 2 + rr;
                float e[7];
                float mx = -1e30f;
                #pragma unroll
                for (int j = 0; j < 7; j++) {
                    int m = lane + 32 * j;
                    float vva = (m < NPIX) ? S[r * 204 + m] : -1e30f;
                    e[j] = vva;
                    mx = fmaxf(mx, vva);
                }
                #pragma unroll
                for (int off = 16; off; off >>= 1)
                    mx = fmaxf(mx, __shfl_xor_sync(0xffffffffu, mx, off));
                float sum = 0.f;
                #pragma unroll
                for (int j = 0; j < 7; j++) { e[j] = __expf(e[j] - mx); sum += e[j]; }
                #pragma unroll
                for (int off = 16; off; off >>= 1)
                    sum += __shfl_xor_sync(0xffffffffu, sum, off);
                float inv = 1.0f / sum;
                #pragma unroll
                for (int j = 0; j < 7; j++) {
                    int m = lane + 32 * j;
                    if (m < NPIX) S[r * 204 + m] = to_tf32(e[j] * inv);
                }
                if (lane < 8) S[r * 204 + 196 + lane] = 0.f;
            }
            __syncthreads();

            // D3: AV  warp = (row-half, d-block): 16 single-chain warps
            {
                const int half = warp >> 3;
                const int d0c  = (warp & 7) * 8;
                const int h16  = half * 16;
                float dd[4] = {0.f, 0.f, 0.f, 0.f};
                #pragma unroll
                for (int ks = 0; ks < 25; ks++) {
                    const int k0 = ks * 8 + tig;
                    float b0 = vv[(d0c + g) * 204 + k0];
                    float b1 = vv[(d0c + g) * 204 + k0 + 4];
                    mma8(dd, S[(h16 + g) * 204 + k0],     S[(h16 + g + 8) * 204 + k0],
                             S[(h16 + g) * 204 + k0 + 4], S[(h16 + g + 8) * 204 + k0 + 4],
                             b0, b1);
                }
                const int dc = d0c + 2 * tig;
                float* gcb = g_cat_t + ((size_t)b * NPIX) * DIM + i * DD;
                int nA = r0 + h16 + g;
                int nB = nA + 8;
                if (nA < NPIX) {
                    *(float2*)&featT[nA * 68 + dc] = make_float2(dd[0], dd[1]);
                    *(float2*)&gcb[(size_t)nA * DIM + dc] =
                        make_float2(to_tf32(fmaxf(dd[0], 0.f)), to_tf32(fmaxf(dd[1], 0.f)));
                }
                if (nB < NPIX) {
                    *(float2*)&featT[nB * 68 + dc] = make_float2(dd[2], dd[3]);
                    *(float2*)&gcb[(size_t)nB * DIM + dc] =
                        make_float2(to_tf32(fmaxf(dd[2], 0.f)), to_tf32(fmaxf(dd[3], 0.f)));
                }
            }
            __syncthreads();
        }
    }
}

// ---------------- prep kernels ----------------
__global__ void wprep_kernel(const float* __restrict__ proj_w) {
    int idx = blockIdx.x * 256 + threadIdx.x;
    g_wt[idx] = to_tf32(proj_w[idx]);
}
__global__ void abprep_kernel(const float* __restrict__ attention_biases,
                              const int* __restrict__ bias_idxs) {
    int idx = blockIdx.x * 256 + threadIdx.x;
    if (idx < NH * NPIX * NPIX) {
        int h = idx / (NPIX * NPIX);
        int nm = idx - h * (NPIX * NPIX);
        g_abmat[idx] = attention_biases[h * NPIX + bias_idxs[nm]];
    }
}

// ---------------- proj kernel: mma.sync tf32 GEMM ----------------
#define PJ_NT 128
#define PJ_AS 36
#define PJ_A_FLOATS (256 * PJ_AS)
#define PJ_B_FLOATS (128 * PJ_AS)
#define PJ_BUF_FLOATS (PJ_A_FLOATS + PJ_B_FLOATS)
#define PJ_SMEM_BYTES (2 * PJ_BUF_FLOATS * 4)

__global__ void __launch_bounds__(256, 1)
proj_mma_kernel(const float* __restrict__ proj_scale,
                const float* __restrict__ proj_bias,
                float* __restrict__ out)
{
    extern __shared__ float smf[];
    const uint32_t smem_base = smem_u32(smf);

    const int tid  = threadIdx.x;
    const int wid  = tid >> 5;
    const int lane = tid & 31;
    const int g    = lane >> 2;
    const int tig  = lane & 3;
    const int n0   = blockIdx.x * PJ_NT;

    const int o0 = (wid & 3) * 64;
    const int nb = (wid >> 2) * 64;

    float acc[4][8][4];
    #pragma unroll
    for (int mi = 0; mi < 4; mi++)
        #pragma unroll
        for (int ni = 0; ni < 8; ni++)
            #pragma unroll
            for (int c = 0; c < 4; c++) acc[mi][ni][c] = 0.f;

    auto issue_chunk = [&](int c) {
        const int buf = c & 1;
        const int k0 = c * 32;
        const uint32_t abase = smem_base + (uint32_t)(buf * PJ_BUF_FLOATS) * 4u;
        const uint32_t bbase = abase + (uint32_t)PJ_A_FLOATS * 4u;
        #pragma unroll
        for (int it = 0; it < 8; it++) {
            int idx = it * 256 + tid;
            int row = idx >> 3, k4 = idx & 7;
            CP_ASYNC16(abase + (uint32_t)(row * PJ_AS + k4 * 4) * 4u,
                       g_wt + (size_t)row * 256 + k0 + k4 * 4);
        }
        #pragma unroll
        for (int it = 0; it < 4; it++) {
            int idx = it * 256 + tid;
            int row = idx >> 3, k4 = idx & 7;
            CP_ASYNC16(bbase + (uint32_t)(row * PJ_AS + k4 * 4) * 4u,
                       g_cat_t + (size_t)(n0 + row) * 256 + k0 + k4 * 4);
        }
        CP_COMMIT();
    };

    issue_chunk(0);

    for (int c = 0; c < 8; c++) {
        CP_WAIT0();
        __syncthreads();
        if (c < 7) issue_chunk(c + 1);

        const int buf = c & 1;
        const uint32_t* Asu = (const uint32_t*)(smf + buf * PJ_BUF_FLOATS);
        const uint32_t* Bsu = Asu + PJ_A_FLOATS;
        const int a_base = (o0 + g) * PJ_AS + tig;
        const int b_base = (nb + g) * PJ_AS + tig;

        #pragma unroll
        for (int k8 = 0; k8 < 32; k8 += 8) {
            uint32_t a[4][4];
            #pragma unroll
            for (int mi = 0; mi < 4; mi++) {
                int ab = a_base + mi * (16 * PJ_AS) + k8;
                a[mi][0] = Asu[ab];
                a[mi][1] = Asu[ab + 8 * PJ_AS];
                a[mi][2] = Asu[ab + 4];
                a[mi][3] = Asu[ab + 8 * PJ_AS + 4];
            }
            uint32_t bfr[8][2];
            #pragma unroll
            for (int ni = 0; ni < 8; ni++) {
                int bb = b_base + ni * (8 * PJ_AS) + k8;
                bfr[ni][0] = Bsu[bb];
                bfr[ni][1] = Bsu[bb + 4];
            }
            #pragma unroll
            for (int mi = 0; mi < 4; mi++)
                #pragma unroll
                for (int ni = 0; ni < 8; ni++)
                    mma_tf32(acc[mi][ni], a[mi], bfr[ni]);
        }
        __syncthreads();
    }

    float* Ssm = smf;
    #pragma unroll
    for (int h = 0; h < 2; h++) {
        __syncthreads();
        if ((wid >> 2) == h) {
            #pragma unroll
            for (int mi = 0; mi < 4; mi++) {
                int orow = o0 + mi * 16 + g;
                #pragma unroll
                for (int ni = 0; ni < 8; ni++) {
                    int nl = ni * 8 + 2 * tig;
                    *(float2*)&Ssm[orow * 68 + nl] =
                        make_float2(acc[mi][ni][0], acc[mi][ni][1]);
                    *(float2*)&Ssm[(orow + 8) * 68 + nl] =
                        make_float2(acc[mi][ni][2], acc[mi][ni][3]);
                }
            }
        }
        __syncthreads();
        #pragma unroll 4
        for (int it = 0; it < 64; it++) {
            int idx = it * 256 + tid;
            int o = idx >> 6, nn = idx & 63;
            float v = Ssm[o * 68 + nn];
            v = v * proj_scale[o] + proj_bias[o];
            unsigned ng = (unsigned)(n0 + h * 64 + nn);
            unsigned bb = ng / 196u;
            unsigned pp = ng - bb * 196u;
            out[(size_t)bb * (DIM * NPIX) + (size_t)o * NPIX + pp] = v;
        }
    }
}

extern "C" void kernel_launch(void* const* d_in, const int* in_sizes, int n_in,
                              void* d_out, int out_size)
{
    (void)in_sizes; (void)n_in; (void)out_size;
    const float* x          = (const float*)d_in[0];
    const float* qkv_w      = (const float*)d_in[1];
    const float* qkv_scale  = (const float*)d_in[2];
    const float* qkv_bias   = (const float*)d_in[3];
    const float* dw_w       = (const float*)d_in[4];
    const float* dw_scale   = (const float*)d_in[5];
    const float* dw_bias    = (const float*)d_in[6];
    const float* proj_w     = (const float*)d_in[7];
    const float* proj_scale = (const float*)d_in[8];
    const float* proj_bias  = (const float*)d_in[9];
    const float* attn_b     = (const float*)d_in[10];
    const int*   bias_idxs  = (const int*)d_in[11];
    float* out = (float*)d_out;

    cudaFuncSetAttribute(cascade_kernel, cudaFuncAttributeMaxDynamicSharedMemorySize, SMEM1_BYTES);
    cudaFuncSetAttribute(proj_mma_kernel, cudaFuncAttributeMaxDynamicSharedMemorySize, PJ_SMEM_BYTES);

    wprep_kernel<<<DIM * DIM / 256, 256>>>(proj_w);
    abprep_kernel<<<(NH * NPIX * NPIX + 255) / 256, 256>>>(attn_b, bias_idxs);
    cascade_kernel<<<BATCH, 512, SMEM1_BYTES>>>(x, qkv_w, qkv_scale, qkv_bias,
                                                dw_w, dw_scale, dw_bias);
    proj_mma_kernel<<<(BATCH * NPIX) / PJ_NT, 256, PJ_SMEM_BYTES>>>(proj_scale, proj_bias, out);
}

// round 6
// speedup vs baseline: 2.2904x; 1.0165x over previous
#include <cuda_runtime.h>
#include <math.h>
#include <cstdint>

// ---------------- problem constants ----------------
#define BATCH 512
#define NH 4
#define KD 16
#define DD 64
#define DIM 256
#define QO 96
#define RESX 14
#define NPIX 196

typedef unsigned long long ull;

// global scratch: relu'd concat of head outputs, PIXEL-MAJOR [b*196+n][c], tf32-rounded
__device__ __align__(128) float g_cat_t[(size_t)BATCH * NPIX * DIM];
// tf32-rounded proj weights
__device__ __align__(128) float g_wt[DIM * DIM];
// pre-gathered attention bias matrices [h][n][m] (+pad)
__device__ __align__(128) float g_abmat[NH * NPIX * NPIX + 16];

__device__ __forceinline__ float to_tf32(float x) {
    float r; asm("cvt.rna.satfinite.tf32.f32 %0, %1;" : "=f"(r) : "f"(x)); return r;
}
__device__ __forceinline__ uint32_t smem_u32(const void* p) {
    uint32_t a;
    asm("{ .reg .u64 t; cvta.to.shared.u64 t, %1; cvt.u32.u64 %0, t; }" : "=r"(a) : "l"(p));
    return a;
}
// fragment-pack permutation: block of 8 cols -> pairs (j, j+4) adjacent
__device__ __forceinline__ int pidx(int m) {
    return (m & ~7) + ((m & 3) * 2) + ((m >> 2) & 1);
}

// ---------------- cp.async helpers ----------------
#define CP_ASYNC16(dst_u32, src_ptr) \
    asm volatile("cp.async.cg.shared.global [%0], [%1], 16;" :: "r"(dst_u32), "l"(src_ptr))
#define CP_COMMIT() asm volatile("cp.async.commit_group;" ::: "memory")
#define CP_WAIT0()  asm volatile("cp.async.wait_group 0;" ::: "memory")

// ---------------- mma.sync tf32 m16n8k8 ----------------
__device__ __forceinline__ void mma_tf32(float* d, const uint32_t* a, const uint32_t* b) {
    asm volatile(
        "mma.sync.aligned.m16n8k8.row.col.f32.tf32.tf32.f32 "
        "{%0,%1,%2,%3}, {%4,%5,%6,%7}, {%8,%9}, {%0,%1,%2,%3};"
        : "+f"(d[0]), "+f"(d[1]), "+f"(d[2]), "+f"(d[3])
        : "r"(a[0]), "r"(a[1]), "r"(a[2]), "r"(a[3]), "r"(b[0]), "r"(b[1]));
}
__device__ __forceinline__ void mma8(float* d, float a0, float a1, float a2, float a3,
                                     float b0, float b1) {
    uint32_t A[4] = {__float_as_uint(a0), __float_as_uint(a1),
                     __float_as_uint(a2), __float_as_uint(a3)};
    uint32_t B[2] = {__float_as_uint(b0), __float_as_uint(b1)};
    mma_tf32(d, A, B);
}

// ---------------- cascade smem layout (float offsets) ----------------
#define CF_FEAT 0            // 200 x 68
#define CF_QT   13600        // 224 x 18
#define CF_KT   17632        // 224 x 18
#define CF_QG   21664        // 224 x 18
#define CF_V    25696        // 64 x 200  packed
#define CF_S    38496        // 64 x 200  packed  (aliases wq)
#define CF_WQ   CF_S         // 96 x 68
#define CF_QSC  51296
#define CF_QBI  51392
#define CF_DSC  51488
#define CF_DBI  51504
#define CF_DWW  51520
#define CF_END  51920
#define SMEM1_BYTES (CF_END * 4)      // 207680

__global__ void __launch_bounds__(512, 1)
cascade_kernel(const float* __restrict__ x,
               const float* __restrict__ qkv_w,
               const float* __restrict__ qkv_scale,
               const float* __restrict__ qkv_bias,
               const float* __restrict__ dw_w,
               const float* __restrict__ dw_scale,
               const float* __restrict__ dw_bias)
{
    extern __shared__ float sm[];
    float* featT = sm + CF_FEAT;
    float* qT    = sm + CF_QT;
    float* kT    = sm + CF_KT;
    float* qgT   = sm + CF_QG;
    float* vv    = sm + CF_V;
    float* S     = sm + CF_S;
    float* wq    = sm + CF_WQ;
    float* qsc   = sm + CF_QSC;
    float* qbi   = sm + CF_QBI;
    float* dsc   = sm + CF_DSC;
    float* dbi   = sm + CF_DBI;
    float* dww   = sm + CF_DWW;

    const int b    = blockIdx.x;
    const int tid  = threadIdx.x;
    const int warp = tid >> 5;    // 0..15
    const int lane = tid & 31;
    const int g    = lane >> 2;   // 0..7
    const int tig  = lane & 3;    // 0..3

    // one-time zero padding
    for (int idx = tid; idx < 28 * 18; idx += 512) qgT[196 * 18 + idx] = 0.f;
    for (int idx = tid; idx < 4 * 68; idx += 512)  featT[196 * 68 + idx] = 0.f;
    if (tid < 256) {                               // vv pad cols 196..199 (slots 193,195,197,199)
        int d = tid >> 2, s = tid & 3;
        vv[d * 200 + 193 + 2 * s] = 0.f;
    }
    __syncthreads();

    for (int i = 0; i < NH; i++) {
        // ---------- Phase A: feat accumulate (tf32-rounded) + weight staging ----------
        {
            const float* xb = x + ((size_t)b * DIM + i * DD) * NPIX;
            if (i == 0) {
                for (int idx = tid; idx < DD * NPIX; idx += 512) {
                    int c = idx / NPIX, n = idx - c * NPIX;
                    featT[n * 68 + c] = to_tf32(xb[idx]);
                }
            } else {
                for (int idx = tid; idx < DD * NPIX; idx += 512) {
                    int c = idx / NPIX, n = idx - c * NPIX;
                    featT[n * 68 + c] = to_tf32(featT[n * 68 + c] + xb[idx]);
                }
            }
            for (int idx = tid; idx < QO * 64; idx += 512)
                wq[(idx >> 6) * 68 + (idx & 63)] = to_tf32(qkv_w[i * QO * 64 + idx]);
            if (tid < 400) dww[tid] = dw_w[i * 400 + tid];
            if (tid >= 416 && tid < 416 + QO) {
                int o = tid - 416;
                qsc[o] = qkv_scale[i * QO + o]; qbi[o] = qkv_bias[i * QO + o];
            }
            if (tid >= 480 && tid < 480 + KD) {
                int c = tid - 480;
                dsc[c] = dw_scale[i * KD + c]; dbi[c] = dw_bias[i * KD + c];
            }
        }
        __syncthreads();

        // ---------- Phase B: QKV via mma, 75 (nt,mp) tasks ----------
        for (int t = warp; t < 75; t += 16) {
            const int nt = t / 3, mp = t - nt * 3;
            const int nb0 = nt * 8;
            float B0[8], B1[8];
            #pragma unroll
            for (int ks = 0; ks < 8; ks++) {
                B0[ks] = featT[(nb0 + g) * 68 + ks * 8 + tig];
                B1[ks] = featT[(nb0 + g) * 68 + ks * 8 + tig + 4];
            }
            const int oX = (2 * mp) * 16, oY = (2 * mp + 1) * 16;
            float dd0[4] = {0.f, 0.f, 0.f, 0.f};
            float dd1[4] = {0.f, 0.f, 0.f, 0.f};
            #pragma unroll
            for (int ks = 0; ks < 8; ks++) {
                mma8(dd0, wq[(oX + g) * 68 + ks * 8 + tig],
                          wq[(oX + g + 8) * 68 + ks * 8 + tig],
                          wq[(oX + g) * 68 + ks * 8 + tig + 4],
                          wq[(oX + g + 8) * 68 + ks * 8 + tig + 4],
                          B0[ks], B1[ks]);
                mma8(dd1, wq[(oY + g) * 68 + ks * 8 + tig],
                          wq[(oY + g + 8) * 68 + ks * 8 + tig],
                          wq[(oY + g) * 68 + ks * 8 + tig + 4],
                          wq[(oY + g + 8) * 68 + ks * 8 + tig + 4],
                          B0[ks], B1[ks]);
            }
            #pragma unroll
            for (int h = 0; h < 2; h++) {
                const int mt = 2 * mp + h;
                float* dd = h ? dd1 : dd0;
                const int oA = mt * 16 + g, oB = oA + 8;
                const float sA = qsc[oA], bA = qbi[oA];
                const float sB = qsc[oB], bB = qbi[oB];
                float y0 = dd[0] * sA + bA, y1 = dd[1] * sA + bA;
                float y2 = dd[2] * sB + bB, y3 = dd[3] * sB + bB;
                const int nc = nb0 + 2 * tig;
                if (mt == 0) {
                    qT[nc * 18 + oA] = y0; qT[(nc + 1) * 18 + oA] = y1;
                    qT[nc * 18 + oB] = y2; qT[(nc + 1) * 18 + oB] = y3;
                } else if (mt == 1) {
                    int c0 = oA - 16, c1 = oB - 16;
                    kT[nc * 18 + c0] = to_tf32(y0); kT[(nc + 1) * 18 + c0] = to_tf32(y1);
                    kT[nc * 18 + c1] = to_tf32(y2); kT[(nc + 1) * 18 + c1] = to_tf32(y3);
                } else {
                    int dA = oA - 32, dB = oB - 32;
                    if (nc < 196) {
                        vv[dA * 200 + pidx(nc)] = to_tf32(y0);
                        vv[dB * 200 + pidx(nc)] = to_tf32(y2);
                    }
                    if (nc + 1 < 196) {
                        vv[dA * 200 + pidx(nc + 1)] = to_tf32(y1);
                        vv[dB * 200 + pidx(nc + 1)] = to_tf32(y3);
                    }
                }
            }
        }
        __syncthreads();

        // ---------- Phase C: depthwise 5x5 conv + affine + exact GELU + residual ----------
        for (int t = tid; t < KD * NPIX; t += 512) {
            int n = t >> 4, c = t & 15;
            int py = n / RESX, px = n - py * RESX;
            float s = 0.f;
            #pragma unroll
            for (int dy = 0; dy < 5; dy++) {
                int yy = py + dy - 2;
                if (yy < 0 || yy >= RESX) continue;
                #pragma unroll
                for (int dx = 0; dx < 5; dx++) {
                    int xx = px + dx - 2;
                    if (xx < 0 || xx >= RESX) continue;
                    s += dww[c * 25 + dy * 5 + dx] * qT[(yy * RESX + xx) * 18 + c];
                }
            }
            float dq = s * dsc[c] + dbi[c];
            float gl = 0.5f * dq * (1.0f + erff(dq * 0.70710678118654752440f));
            qgT[n * 18 + c] = to_tf32(gl + qT[n * 18 + c]);
        }
        __syncthreads();

        const float* abm = g_abmat + (size_t)i * (NPIX * NPIX);

        // ---------- Phase D: attention in 64-row tiles (3 full + 1 tail of 4) ----------
        for (int t32 = 0; t32 < 4; t32++) {
            const int r0 = t32 * 64;
            const int rows = (t32 < 3) ? 64 : 4;
            const int mts  = (t32 < 3) ? 4 : 1;

            // D1: QK  S[n][m] = qg[n]·k[m] * 0.25 + bias   (mts*25 tasks)
            for (int t = warp; t < mts * 25; t += 16) {
                const int mt = t / 25, nt = t - mt * 25;
                const int mm0 = nt * 8;
                float b00 = kT[(mm0 + g) * 18 + tig],     b01 = kT[(mm0 + g) * 18 + tig + 4];
                float b10 = kT[(mm0 + g) * 18 + tig + 8], b11 = kT[(mm0 + g) * 18 + tig + 12];
                const int rr = r0 + mt * 16;
                float dd[4] = {0.f, 0.f, 0.f, 0.f};
                mma8(dd, qgT[(rr + g) * 18 + tig],     qgT[(rr + g + 8) * 18 + tig],
                         qgT[(rr + g) * 18 + tig + 4], qgT[(rr + g + 8) * 18 + tig + 4],
                         b00, b01);
                mma8(dd, qgT[(rr + g) * 18 + tig + 8],  qgT[(rr + g + 8) * 18 + tig + 8],
                         qgT[(rr + g) * 18 + tig + 12], qgT[(rr + g + 8) * 18 + tig + 12],
                         b10, b11);
                const int nlA = mt * 16 + g, nlB = nlA + 8;
                const int ngA = min(r0 + nlA, 195), ngB = min(r0 + nlB, 195);
                const int m0 = mm0 + 2 * tig;
                float2 abA = *(const float2*)&abm[(size_t)ngA * NPIX + m0];
                float2 abB = *(const float2*)&abm[(size_t)ngB * NPIX + m0];
                S[nlA * 200 + pidx(m0)]     = dd[0] * 0.25f + abA.x;
                S[nlA * 200 + pidx(m0 + 1)] = dd[1] * 0.25f + abA.y;
                S[nlB * 200 + pidx(m0)]     = dd[2] * 0.25f + abB.x;
                S[nlB * 200 + pidx(m0 + 1)] = dd[3] * 0.25f + abB.y;
            }
            __syncthreads();

            // D2: softmax (packed addressing), zero pad slots
            for (int r = warp; r < rows; r += 16) {
                float e[7];
                float mx = -1e30f;
                #pragma unroll
                for (int j = 0; j < 7; j++) {
                    int m = lane + 32 * j;
                    float vva = (m < NPIX) ? S[r * 200 + pidx(m)] : -1e30f;
                    e[j] = vva;
                    mx = fmaxf(mx, vva);
                }
                #pragma unroll
                for (int off = 16; off; off >>= 1)
                    mx = fmaxf(mx, __shfl_xor_sync(0xffffffffu, mx, off));
                float sum = 0.f;
                #pragma unroll
                for (int j = 0; j < 7; j++) { e[j] = __expf(e[j] - mx); sum += e[j]; }
                #pragma unroll
                for (int off = 16; off; off >>= 1)
                    sum += __shfl_xor_sync(0xffffffffu, sum, off);
                float inv = 1.0f / sum;
                #pragma unroll
                for (int j = 0; j < 7; j++) {
                    int m = lane + 32 * j;
                    if (m < NPIX) S[r * 200 + pidx(m)] = to_tf32(e[j] * inv);
                }
                if (lane < 4) S[r * 200 + 193 + 2 * lane] = 0.f;
            }
            __syncthreads();

            // D3: AV with packed LDS.64 operands
            float* gcb = g_cat_t + ((size_t)b * NPIX) * DIM + i * DD;
            if (t32 < 3) {
                const int db = warp & 7;
                const int qa = warp >> 3;             // quarters qa and qa+2
                const int d0c = db * 8;
                const int rl0 = qa * 16 + g,        rh0 = rl0 + 8;
                const int rl1 = (qa + 2) * 16 + g,  rh1 = rl1 + 8;
                float dd0[4] = {0.f, 0.f, 0.f, 0.f};
                float dd1[4] = {0.f, 0.f, 0.f, 0.f};
                #pragma unroll
                for (int ks = 0; ks < 25; ks++) {
                    const int ko = ks * 8 + tig * 2;
                    float2 bv = *(const float2*)&vv[(d0c + g) * 200 + ko];
                    float2 l0 = *(const float2*)&S[rl0 * 200 + ko];
                    float2 h0 = *(const float2*)&S[rh0 * 200 + ko];
                    float2 l1 = *(const float2*)&S[rl1 * 200 + ko];
                    float2 h1 = *(const float2*)&S[rh1 * 200 + ko];
                    mma8(dd0, l0.x, h0.x, l0.y, h0.y, bv.x, bv.y);
                    mma8(dd1, l1.x, h1.x, l1.y, h1.y, bv.x, bv.y);
                }
                const int dc = d0c + 2 * tig;
                #pragma unroll
                for (int h = 0; h < 2; h++) {
                    float* dd = h ? dd1 : dd0;
                    int nA = r0 + (h ? rl1 : rl0);
                    int nB = nA + 8;
                    *(float2*)&featT[nA * 68 + dc] = make_float2(dd[0], dd[1]);
                    *(float2*)&gcb[(size_t)nA * DIM + dc] =
                        make_float2(to_tf32(fmaxf(dd[0], 0.f)), to_tf32(fmaxf(dd[1], 0.f)));
                    *(float2*)&featT[nB * 68 + dc] = make_float2(dd[2], dd[3]);
                    *(float2*)&gcb[(size_t)nB * DIM + dc] =
                        make_float2(to_tf32(fmaxf(dd[2], 0.f)), to_tf32(fmaxf(dd[3], 0.f)));
                }
            } else if (warp < 8) {
                const int d0c = warp * 8;
                const int rl = g, rh = g + 8;
                float dd[4] = {0.f, 0.f, 0.f, 0.f};
                #pragma unroll
                for (int ks = 0; ks < 25; ks++) {
                    const int ko = ks * 8 + tig * 2;
                    float2 bv = *(const float2*)&vv[(d0c + g) * 200 + ko];
                    float2 l0 = *(const float2*)&S[rl * 200 + ko];
                    float2 h0 = *(const float2*)&S[rh * 200 + ko];
                    mma8(dd, l0.x, h0.x, l0.y, h0.y, bv.x, bv.y);
                }
                const int dc = d0c + 2 * tig;
                int nA = r0 + rl, nB = r0 + rh;
                if (nA < NPIX) {
                    *(float2*)&featT[nA * 68 + dc] = make_float2(dd[0], dd[1]);
                    *(float2*)&gcb[(size_t)nA * DIM + dc] =
                        make_float2(to_tf32(fmaxf(dd[0], 0.f)), to_tf32(fmaxf(dd[1], 0.f)));
                }
                if (nB < NPIX) {
                    *(float2*)&featT[nB * 68 + dc] = make_float2(dd[2], dd[3]);
                    *(float2*)&gcb[(size_t)nB * DIM + dc] =
                        make_float2(to_tf32(fmaxf(dd[2], 0.f)), to_tf32(fmaxf(dd[3], 0.f)));
                }
            }
            __syncthreads();
        }
    }
}

// ---------------- prep kernels ----------------
__global__ void wprep_kernel(const float* __restrict__ proj_w) {
    int idx = blockIdx.x * 256 + threadIdx.x;
    g_wt[idx] = to_tf32(proj_w[idx]);
}
__global__ void abprep_kernel(const float* __restrict__ attention_biases,
                              const int* __restrict__ bias_idxs) {
    int idx = blockIdx.x * 256 + threadIdx.x;
    if (idx < NH * NPIX * NPIX) {
        int h = idx / (NPIX * NPIX);
        int nm = idx - h * (NPIX * NPIX);
        g_abmat[idx] = attention_biases[h * NPIX + bias_idxs[nm]];
    }
}

// ---------------- proj kernel: mma.sync tf32 GEMM ----------------
#define PJ_NT 128
#define PJ_AS 36
#define PJ_A_FLOATS (256 * PJ_AS)
#define PJ_B_FLOATS (128 * PJ_AS)
#define PJ_BUF_FLOATS (PJ_A_FLOATS + PJ_B_FLOATS)
#define PJ_SMEM_BYTES (2 * PJ_BUF_FLOATS * 4)

__global__ void __launch_bounds__(256, 1)
proj_mma_kernel(const float* __restrict__ proj_scale,
                const float* __restrict__ proj_bias,
                float* __restrict__ out)
{
    extern __shared__ float smf[];
    const uint32_t smem_base = smem_u32(smf);

    const int tid  = threadIdx.x;
    const int wid  = tid >> 5;
    const int lane = tid & 31;
    const int g    = lane >> 2;
    const int tig  = lane & 3;
    const int n0   = blockIdx.x * PJ_NT;

    const int o0 = (wid & 3) * 64;
    const int nb = (wid >> 2) * 64;

    float acc[4][8][4];
    #pragma unroll
    for (int mi = 0; mi < 4; mi++)
        #pragma unroll
        for (int ni = 0; ni < 8; ni++)
            #pragma unroll
            for (int c = 0; c < 4; c++) acc[mi][ni][c] = 0.f;

    auto issue_chunk = [&](int c) {
        const int buf = c & 1;
        const int k0 = c * 32;
        const uint32_t abase = smem_base + (uint32_t)(buf * PJ_BUF_FLOATS) * 4u;
        const uint32_t bbase = abase + (uint32_t)PJ_A_FLOATS * 4u;
        #pragma unroll
        for (int it = 0; it < 8; it++) {
            int idx = it * 256 + tid;
            int row = idx >> 3, k4 = idx & 7;
            CP_ASYNC16(abase + (uint32_t)(row * PJ_AS + k4 * 4) * 4u,
                       g_wt + (size_t)row * 256 + k0 + k4 * 4);
        }
        #pragma unroll
        for (int it = 0; it < 4; it++) {
            int idx = it * 256 + tid;
            int row = idx >> 3, k4 = idx & 7;
            CP_ASYNC16(bbase + (uint32_t)(row * PJ_AS + k4 * 4) * 4u,
                       g_cat_t + (size_t)(n0 + row) * 256 + k0 + k4 * 4);
        }
        CP_COMMIT();
    };

    issue_chunk(0);

    for (int c = 0; c < 8; c++) {
        CP_WAIT0();
        __syncthreads();
        if (c < 7) issue_chunk(c + 1);

        const int buf = c & 1;
        const uint32_t* Asu = (const uint32_t*)(smf + buf * PJ_BUF_FLOATS);
        const uint32_t* Bsu = Asu + PJ_A_FLOATS;
        const int a_base = (o0 + g) * PJ_AS + tig;
        const int b_base = (nb + g) * PJ_AS + tig;

        #pragma unroll
        for (int k8 = 0; k8 < 32; k8 += 8) {
            uint32_t a[4][4];
            #pragma unroll
            for (int mi = 0; mi < 4; mi++) {
                int ab = a_base + mi * (16 * PJ_AS) + k8;
                a[mi][0] = Asu[ab];
                a[mi][1] = Asu[ab + 8 * PJ_AS];
                a[mi][2] = Asu[ab + 4];
                a[mi][3] = Asu[ab + 8 * PJ_AS + 4];
            }
            uint32_t bfr[8][2];
            #pragma unroll
            for (int ni = 0; ni < 8; ni++) {
                int bb = b_base + ni * (8 * PJ_AS) + k8;
                bfr[ni][0] = Bsu[bb];
                bfr[ni][1] = Bsu[bb + 4];
            }
            #pragma unroll
            for (int mi = 0; mi < 4; mi++)
                #pragma unroll
                for (int ni = 0; ni < 8; ni++)
                    mma_tf32(acc[mi][ni], a[mi], bfr[ni]);
        }
        __syncthreads();
    }

    float* Ssm = smf;
    #pragma unroll
    for (int h = 0; h < 2; h++) {
        __syncthreads();
        if ((wid >> 2) == h) {
            #pragma unroll
            for (int mi = 0; mi < 4; mi++) {
                int orow = o0 + mi * 16 + g;
                #pragma unroll
                for (int ni = 0; ni < 8; ni++) {
                    int nl = ni * 8 + 2 * tig;
                    *(float2*)&Ssm[orow * 68 + nl] =
                        make_float2(acc[mi][ni][0], acc[mi][ni][1]);
                    *(float2*)&Ssm[(orow + 8) * 68 + nl] =
                        make_float2(acc[mi][ni][2], acc[mi][ni][3]);
                }
            }
        }
        __syncthreads();
        #pragma unroll 4
        for (int it = 0; it < 64; it++) {
            int idx = it * 256 + tid;
            int o = idx >> 6, nn = idx & 63;
            float v = Ssm[o * 68 + nn];
            v = v * proj_scale[o] + proj_bias[o];
            unsigned ng = (unsigned)(n0 + h * 64 + nn);
            unsigned bb = ng / 196u;
            unsigned pp = ng - bb * 196u;
            out[(size_t)bb * (DIM * NPIX) + (size_t)o * NPIX + pp] = v;
        }
    }
}

extern "C" void kernel_launch(void* const* d_in, const int* in_sizes, int n_in,
                              void* d_out, int out_size)
{
    (void)in_sizes; (void)n_in; (void)out_size;
    const float* x          = (const float*)d_in[0];
    const float* qkv_w      = (const float*)d_in[1];
    const float* qkv_scale  = (const float*)d_in[2];
    const float* qkv_bias   = (const float*)d_in[3];
    const float* dw_w       = (const float*)d_in[4];
    const float* dw_scale   = (const float*)d_in[5];
    const float* dw_bias    = (const float*)d_in[6];
    const float* proj_w     = (const float*)d_in[7];
    const float* proj_scale = (const float*)d_in[8];
    const float* proj_bias  = (const float*)d_in[9];
    const float* attn_b     = (const float*)d_in[10];
    const int*   bias_idxs  = (const int*)d_in[11];
    float* out = (float*)d_out;

    cudaFuncSetAttribute(cascade_kernel, cudaFuncAttributeMaxDynamicSharedMemorySize, SMEM1_BYTES);
    cudaFuncSetAttribute(proj_mma_kernel, cudaFuncAttributeMaxDynamicSharedMemorySize, PJ_SMEM_BYTES);

    wprep_kernel<<<DIM * DIM / 256, 256>>>(proj_w);
    abprep_kernel<<<(NH * NPIX * NPIX + 255) / 256, 256>>>(attn_b, bias_idxs);
    cascade_kernel<<<BATCH, 512, SMEM1_BYTES>>>(x, qkv_w, qkv_scale, qkv_bias,
                                                dw_w, dw_scale, dw_bias);
    proj_mma_kernel<<<(BATCH * NPIX) / PJ_NT, 256, PJ_SMEM_BYTES>>>(proj_scale, proj_bias, out);
}

// round 7
// speedup vs baseline: 2.4331x; 1.0623x over previous
#include <cuda_runtime.h>
#include <math.h>
#include <cstdint>

// ---------------- problem constants ----------------
#define BATCH 512
#define NH 4
#define KD 16
#define DD 64
#define DIM 256
#define QO 96
#define RESX 14
#define NPIX 196

typedef unsigned long long ull;

// global scratch: relu'd concat of head outputs, PIXEL-MAJOR [b*196+n][c], tf32-rounded
__device__ __align__(128) float g_cat_t[(size_t)BATCH * NPIX * DIM];
// tf32-rounded proj weights
__device__ __align__(128) float g_wt[DIM * DIM];
// pre-gathered attention bias matrices [h][n][m] (+pad)
__device__ __align__(128) float g_abmat[NH * NPIX * NPIX + 16];

__device__ __forceinline__ float to_tf32(float x) {
    float r; asm("cvt.rna.satfinite.tf32.f32 %0, %1;" : "=f"(r) : "f"(x)); return r;
}
__device__ __forceinline__ uint32_t smem_u32(const void* p) {
    uint32_t a;
    asm("{ .reg .u64 t; cvta.to.shared.u64 t, %1; cvt.u32.u64 %0, t; }" : "=r"(a) : "l"(p));
    return a;
}
// fragment-pack permutation: block of 8 cols -> pairs (j, j+4) adjacent
__device__ __forceinline__ int pidx(int m) {
    return (m & ~7) + ((m & 3) * 2) + ((m >> 2) & 1);
}

// ---------------- cp.async helpers ----------------
#define CP_ASYNC16(dst_u32, src_ptr) \
    asm volatile("cp.async.cg.shared.global [%0], [%1], 16;" :: "r"(dst_u32), "l"(src_ptr))
#define CP_COMMIT() asm volatile("cp.async.commit_group;" ::: "memory")
#define CP_WAIT0()  asm volatile("cp.async.wait_group 0;" ::: "memory")

// ---------------- mma.sync tf32 m16n8k8 ----------------
__device__ __forceinline__ void mma_tf32(float* d, const uint32_t* a, const uint32_t* b) {
    asm volatile(
        "mma.sync.aligned.m16n8k8.row.col.f32.tf32.tf32.f32 "
        "{%0,%1,%2,%3}, {%4,%5,%6,%7}, {%8,%9}, {%0,%1,%2,%3};"
        : "+f"(d[0]), "+f"(d[1]), "+f"(d[2]), "+f"(d[3])
        : "r"(a[0]), "r"(a[1]), "r"(a[2]), "r"(a[3]), "r"(b[0]), "r"(b[1]));
}
__device__ __forceinline__ void mma8(float* d, float a0, float a1, float a2, float a3,
                                     float b0, float b1) {
    uint32_t A[4] = {__float_as_uint(a0), __float_as_uint(a1),
                     __float_as_uint(a2), __float_as_uint(a3)};
    uint32_t B[2] = {__float_as_uint(b0), __float_as_uint(b1)};
    mma_tf32(d, A, B);
}

// ---------------- cascade smem layout (float offsets) ----------------
#define CF_FEAT 0            // 200 x 68
#define CF_QT   13600        // 224 x 18
#define CF_KT   17632        // 224 x 18
#define CF_QG   21664        // 224 x 18
#define CF_V    25696        // 64 x 200  packed
#define CF_S    38496        // 64 x 200  packed  (aliases wq)
#define CF_WQ   CF_S         // 96 x 68
#define CF_QSC  51296
#define CF_QBI  51392
#define CF_DSC  51488
#define CF_DBI  51504
#define CF_DWW  51520
#define CF_END  51920
#define SMEM1_BYTES (CF_END * 4)      // 207680

__global__ void __launch_bounds__(1024, 1)
cascade_kernel(const float* __restrict__ x,
               const float* __restrict__ qkv_w,
               const float* __restrict__ qkv_scale,
               const float* __restrict__ qkv_bias,
               const float* __restrict__ dw_w,
               const float* __restrict__ dw_scale,
               const float* __restrict__ dw_bias)
{
    extern __shared__ float sm[];
    float* featT = sm + CF_FEAT;
    float* qT    = sm + CF_QT;
    float* kT    = sm + CF_KT;
    float* qgT   = sm + CF_QG;
    float* vv    = sm + CF_V;
    float* S     = sm + CF_S;
    float* wq    = sm + CF_WQ;
    float* qsc   = sm + CF_QSC;
    float* qbi   = sm + CF_QBI;
    float* dsc   = sm + CF_DSC;
    float* dbi   = sm + CF_DBI;
    float* dww   = sm + CF_DWW;

    const int b    = blockIdx.x;
    const int tid  = threadIdx.x;
    const int warp = tid >> 5;    // 0..31
    const int lane = tid & 31;
    const int g    = lane >> 2;   // 0..7
    const int tig  = lane & 3;    // 0..3

    // one-time zero padding
    for (int idx = tid; idx < 28 * 18; idx += 1024) qgT[196 * 18 + idx] = 0.f;
    if (tid < 4 * 68) featT[196 * 68 + tid] = 0.f;
    if (tid >= 512 && tid < 768) {                 // vv pad cols (slots 193,195,197,199)
        int t = tid - 512;
        int d = t >> 2, s = t & 3;
        vv[d * 200 + 193 + 2 * s] = 0.f;
    }
    __syncthreads();

    for (int i = 0; i < NH; i++) {
        // ---------- Phase A: feat accumulate (tf32-rounded) + weight staging ----------
        {
            const float* xb = x + ((size_t)b * DIM + i * DD) * NPIX;
            if (i == 0) {
                for (int idx = tid; idx < DD * NPIX; idx += 1024) {
                    int c = idx / NPIX, n = idx - c * NPIX;
                    featT[n * 68 + c] = to_tf32(xb[idx]);
                }
            } else {
                for (int idx = tid; idx < DD * NPIX; idx += 1024) {
                    int c = idx / NPIX, n = idx - c * NPIX;
                    featT[n * 68 + c] = to_tf32(featT[n * 68 + c] + xb[idx]);
                }
            }
            for (int idx = tid; idx < QO * 64; idx += 1024)
                wq[(idx >> 6) * 68 + (idx & 63)] = to_tf32(qkv_w[i * QO * 64 + idx]);
            if (tid < 400) dww[tid] = dw_w[i * 400 + tid];
            if (tid >= 416 && tid < 416 + QO) {
                int o = tid - 416;
                qsc[o] = qkv_scale[i * QO + o]; qbi[o] = qkv_bias[i * QO + o];
            }
            if (tid >= 544 && tid < 544 + KD) {
                int c = tid - 544;
                dsc[c] = dw_scale[i * KD + c]; dbi[c] = dw_bias[i * KD + c];
            }
        }
        __syncthreads();

        // ---------- Phase B: QKV via mma, 75 (nt,mp) tasks over 32 warps ----------
        for (int t = warp; t < 75; t += 32) {
            const int nt = t / 3, mp = t - nt * 3;
            const int nb0 = nt * 8;
            float B0[8], B1[8];
            #pragma unroll
            for (int ks = 0; ks < 8; ks++) {
                B0[ks] = featT[(nb0 + g) * 68 + ks * 8 + tig];
                B1[ks] = featT[(nb0 + g) * 68 + ks * 8 + tig + 4];
            }
            const int oX = (2 * mp) * 16, oY = (2 * mp + 1) * 16;
            float dd0[4] = {0.f, 0.f, 0.f, 0.f};
            float dd1[4] = {0.f, 0.f, 0.f, 0.f};
            #pragma unroll
            for (int ks = 0; ks < 8; ks++) {
                mma8(dd0, wq[(oX + g) * 68 + ks * 8 + tig],
                          wq[(oX + g + 8) * 68 + ks * 8 + tig],
                          wq[(oX + g) * 68 + ks * 8 + tig + 4],
                          wq[(oX + g + 8) * 68 + ks * 8 + tig + 4],
                          B0[ks], B1[ks]);
                mma8(dd1, wq[(oY + g) * 68 + ks * 8 + tig],
                          wq[(oY + g + 8) * 68 + ks * 8 + tig],
                          wq[(oY + g) * 68 + ks * 8 + tig + 4],
                          wq[(oY + g + 8) * 68 + ks * 8 + tig + 4],
                          B0[ks], B1[ks]);
            }
            #pragma unroll
            for (int h = 0; h < 2; h++) {
                const int mt = 2 * mp + h;
                float* dd = h ? dd1 : dd0;
                const int oA = mt * 16 + g, oB = oA + 8;
                const float sA = qsc[oA], bA = qbi[oA];
                const float sB = qsc[oB], bB = qbi[oB];
                float y0 = dd[0] * sA + bA, y1 = dd[1] * sA + bA;
                float y2 = dd[2] * sB + bB, y3 = dd[3] * sB + bB;
                const int nc = nb0 + 2 * tig;
                if (mt == 0) {
                    qT[nc * 18 + oA] = y0; qT[(nc + 1) * 18 + oA] = y1;
                    qT[nc * 18 + oB] = y2; qT[(nc + 1) * 18 + oB] = y3;
                } else if (mt == 1) {
                    int c0 = oA - 16, c1 = oB - 16;
                    kT[nc * 18 + c0] = to_tf32(y0); kT[(nc + 1) * 18 + c0] = to_tf32(y1);
                    kT[nc * 18 + c1] = to_tf32(y2); kT[(nc + 1) * 18 + c1] = to_tf32(y3);
                } else {
                    int dA = oA - 32, dB = oB - 32;
                    if (nc < 196) {
                        vv[dA * 200 + pidx(nc)] = to_tf32(y0);
                        vv[dB * 200 + pidx(nc)] = to_tf32(y2);
                    }
                    if (nc + 1 < 196) {
                        vv[dA * 200 + pidx(nc + 1)] = to_tf32(y1);
                        vv[dB * 200 + pidx(nc + 1)] = to_tf32(y3);
                    }
                }
            }
        }
        __syncthreads();

        // ---------- Phase C: depthwise 5x5 conv + affine + exact GELU + residual ----------
        for (int t = tid; t < KD * NPIX; t += 1024) {
            int n = t >> 4, c = t & 15;
            int py = n / RESX, px = n - py * RESX;
            float s = 0.f;
            #pragma unroll
            for (int dy = 0; dy < 5; dy++) {
                int yy = py + dy - 2;
                if (yy < 0 || yy >= RESX) continue;
                #pragma unroll
                for (int dx = 0; dx < 5; dx++) {
                    int xx = px + dx - 2;
                    if (xx < 0 || xx >= RESX) continue;
                    s += dww[c * 25 + dy * 5 + dx] * qT[(yy * RESX + xx) * 18 + c];
                }
            }
            float dq = s * dsc[c] + dbi[c];
            float gl = 0.5f * dq * (1.0f + erff(dq * 0.70710678118654752440f));
            qgT[n * 18 + c] = to_tf32(gl + qT[n * 18 + c]);
        }
        __syncthreads();

        const float* abm = g_abmat + (size_t)i * (NPIX * NPIX);

        // ---------- Phase D: attention in 64-row tiles (3 full + 1 tail of 4) ----------
        for (int t32 = 0; t32 < 4; t32++) {
            const int r0 = t32 * 64;
            const int rows = (t32 < 3) ? 64 : 4;
            const int mts  = (t32 < 3) ? 4 : 1;

            // D1: QK  S[n][m] = qg[n]·k[m] * 0.25 + bias   (mts*25 tasks, 32 warps)
            for (int t = warp; t < mts * 25; t += 32) {
                const int mt = t / 25, nt = t - mt * 25;
                const int mm0 = nt * 8;
                float b00 = kT[(mm0 + g) * 18 + tig],     b01 = kT[(mm0 + g) * 18 + tig + 4];
                float b10 = kT[(mm0 + g) * 18 + tig + 8], b11 = kT[(mm0 + g) * 18 + tig + 12];
                const int rr = r0 + mt * 16;
                float dd[4] = {0.f, 0.f, 0.f, 0.f};
                mma8(dd, qgT[(rr + g) * 18 + tig],     qgT[(rr + g + 8) * 18 + tig],
                         qgT[(rr + g) * 18 + tig + 4], qgT[(rr + g + 8) * 18 + tig + 4],
                         b00, b01);
                mma8(dd, qgT[(rr + g) * 18 + tig + 8],  qgT[(rr + g + 8) * 18 + tig + 8],
                         qgT[(rr + g) * 18 + tig + 12], qgT[(rr + g + 8) * 18 + tig + 12],
                         b10, b11);
                const int nlA = mt * 16 + g, nlB = nlA + 8;
                const int ngA = min(r0 + nlA, 195), ngB = min(r0 + nlB, 195);
                const int m0 = mm0 + 2 * tig;
                float2 abA = *(const float2*)&abm[(size_t)ngA * NPIX + m0];
                float2 abB = *(const float2*)&abm[(size_t)ngB * NPIX + m0];
                S[nlA * 200 + pidx(m0)]     = dd[0] * 0.25f + abA.x;
                S[nlA * 200 + pidx(m0 + 1)] = dd[1] * 0.25f + abA.y;
                S[nlB * 200 + pidx(m0)]     = dd[2] * 0.25f + abB.x;
                S[nlB * 200 + pidx(m0 + 1)] = dd[3] * 0.25f + abB.y;
            }
            __syncthreads();

            // D2: softmax (packed addressing), zero pad slots
            for (int r = warp; r < rows; r += 32) {
                float e[7];
                float mx = -1e30f;
                #pragma unroll
                for (int j = 0; j < 7; j++) {
                    int m = lane + 32 * j;
                    float vva = (m < NPIX) ? S[r * 200 + pidx(m)] : -1e30f;
                    e[j] = vva;
                    mx = fmaxf(mx, vva);
                }
                #pragma unroll
                for (int off = 16; off; off >>= 1)
                    mx = fmaxf(mx, __shfl_xor_sync(0xffffffffu, mx, off));
                float sum = 0.f;
                #pragma unroll
                for (int j = 0; j < 7; j++) { e[j] = __expf(e[j] - mx); sum += e[j]; }
                #pragma unroll
                for (int off = 16; off; off >>= 1)
                    sum += __shfl_xor_sync(0xffffffffu, sum, off);
                float inv = 1.0f / sum;
                #pragma unroll
                for (int j = 0; j < 7; j++) {
                    int m = lane + 32 * j;
                    if (m < NPIX) S[r * 200 + pidx(m)] = to_tf32(e[j] * inv);
                }
                if (lane < 4) S[r * 200 + 193 + 2 * lane] = 0.f;
            }
            __syncthreads();

            // D3: AV with packed LDS.64 operands (warps 0-15: 2 chains each)
            float* gcb = g_cat_t + ((size_t)b * NPIX) * DIM + i * DD;
            if (t32 < 3) {
                if (warp < 16) {
                    const int db = warp & 7;
                    const int qa = warp >> 3;             // quarters qa and qa+2
                    const int d0c = db * 8;
                    const int rl0 = qa * 16 + g,        rh0 = rl0 + 8;
                    const int rl1 = (qa + 2) * 16 + g,  rh1 = rl1 + 8;
                    float dd0[4] = {0.f, 0.f, 0.f, 0.f};
                    float dd1[4] = {0.f, 0.f, 0.f, 0.f};
                    #pragma unroll
                    for (int ks = 0; ks < 25; ks++) {
                        const int ko = ks * 8 + tig * 2;
                        float2 bv = *(const float2*)&vv[(d0c + g) * 200 + ko];
                        float2 l0 = *(const float2*)&S[rl0 * 200 + ko];
                        float2 h0 = *(const float2*)&S[rh0 * 200 + ko];
                        float2 l1 = *(const float2*)&S[rl1 * 200 + ko];
                        float2 h1 = *(const float2*)&S[rh1 * 200 + ko];
                        mma8(dd0, l0.x, h0.x, l0.y, h0.y, bv.x, bv.y);
                        mma8(dd1, l1.x, h1.x, l1.y, h1.y, bv.x, bv.y);
                    }
                    const int dc = d0c + 2 * tig;
                    #pragma unroll
                    for (int h = 0; h < 2; h++) {
                        float* dd = h ? dd1 : dd0;
                        int nA = r0 + (h ? rl1 : rl0);
                        int nB = nA + 8;
                        *(float2*)&featT[nA * 68 + dc] = make_float2(dd[0], dd[1]);
                        *(float2*)&gcb[(size_t)nA * DIM + dc] =
                            make_float2(to_tf32(fmaxf(dd[0], 0.f)), to_tf32(fmaxf(dd[1], 0.f)));
                        *(float2*)&featT[nB * 68 + dc] = make_float2(dd[2], dd[3]);
                        *(float2*)&gcb[(size_t)nB * DIM + dc] =
                            make_float2(to_tf32(fmaxf(dd[2], 0.f)), to_tf32(fmaxf(dd[3], 0.f)));
                    }
                }
            } else if (warp < 8) {
                const int d0c = warp * 8;
                const int rl = g, rh = g + 8;
                float dd[4] = {0.f, 0.f, 0.f, 0.f};
                #pragma unroll
                for (int ks = 0; ks < 25; ks++) {
                    const int ko = ks * 8 + tig * 2;
                    float2 bv = *(const float2*)&vv[(d0c + g) * 200 + ko];
                    float2 l0 = *(const float2*)&S[rl * 200 + ko];
                    float2 h0 = *(const float2*)&S[rh * 200 + ko];
                    mma8(dd, l0.x, h0.x, l0.y, h0.y, bv.x, bv.y);
                }
                const int dc = d0c + 2 * tig;
                int nA = r0 + rl, nB = r0 + rh;
                if (nA < NPIX) {
                    *(float2*)&featT[nA * 68 + dc] = make_float2(dd[0], dd[1]);
                    *(float2*)&gcb[(size_t)nA * DIM + dc] =
                        make_float2(to_tf32(fmaxf(dd[0], 0.f)), to_tf32(fmaxf(dd[1], 0.f)));
                }
                if (nB < NPIX) {
                    *(float2*)&featT[nB * 68 + dc] = make_float2(dd[2], dd[3]);
                    *(float2*)&gcb[(size_t)nB * DIM + dc] =
                        make_float2(to_tf32(fmaxf(dd[2], 0.f)), to_tf32(fmaxf(dd[3], 0.f)));
                }
            }
            __syncthreads();
        }
    }
}

// ---------------- prep kernels ----------------
__global__ void wprep_kernel(const float* __restrict__ proj_w) {
    int idx = blockIdx.x * 256 + threadIdx.x;
    g_wt[idx] = to_tf32(proj_w[idx]);
}
__global__ void abprep_kernel(const float* __restrict__ attention_biases,
                              const int* __restrict__ bias_idxs) {
    int idx = blockIdx.x * 256 + threadIdx.x;
    if (idx < NH * NPIX * NPIX) {
        int h = idx / (NPIX * NPIX);
        int nm = idx - h * (NPIX * NPIX);
        g_abmat[idx] = attention_biases[h * NPIX + bias_idxs[nm]];
    }
}

// ---------------- proj kernel: mma.sync tf32 GEMM ----------------
#define PJ_NT 128
#define PJ_AS 36
#define PJ_A_FLOATS (256 * PJ_AS)
#define PJ_B_FLOATS (128 * PJ_AS)
#define PJ_BUF_FLOATS (PJ_A_FLOATS + PJ_B_FLOATS)
#define PJ_SMEM_BYTES (2 * PJ_BUF_FLOATS * 4)

__global__ void __launch_bounds__(256, 1)
proj_mma_kernel(const float* __restrict__ proj_scale,
                const float* __restrict__ proj_bias,
                float* __restrict__ out)
{
    extern __shared__ float smf[];
    const uint32_t smem_base = smem_u32(smf);

    const int tid  = threadIdx.x;
    const int wid  = tid >> 5;
    const int lane = tid & 31;
    const int g    = lane >> 2;
    const int tig  = lane & 3;
    const int n0   = blockIdx.x * PJ_NT;

    const int o0 = (wid & 3) * 64;
    const int nb = (wid >> 2) * 64;

    float acc[4][8][4];
    #pragma unroll
    for (int mi = 0; mi < 4; mi++)
        #pragma unroll
        for (int ni = 0; ni < 8; ni++)
            #pragma unroll
            for (int c = 0; c < 4; c++) acc[mi][ni][c] = 0.f;

    auto issue_chunk = [&](int c) {
        const int buf = c & 1;
        const int k0 = c * 32;
        const uint32_t abase = smem_base + (uint32_t)(buf * PJ_BUF_FLOATS) * 4u;
        const uint32_t bbase = abase + (uint32_t)PJ_A_FLOATS * 4u;
        #pragma unroll
        for (int it = 0; it < 8; it++) {
            int idx = it * 256 + tid;
            int row = idx >> 3, k4 = idx & 7;
            CP_ASYNC16(abase + (uint32_t)(row * PJ_AS + k4 * 4) * 4u,
                       g_wt + (size_t)row * 256 + k0 + k4 * 4);
        }
        #pragma unroll
        for (int it = 0; it < 4; it++) {
            int idx = it * 256 + tid;
            int row = idx >> 3, k4 = idx & 7;
            CP_ASYNC16(bbase + (uint32_t)(row * PJ_AS + k4 * 4) * 4u,
                       g_cat_t + (size_t)(n0 + row) * 256 + k0 + k4 * 4);
        }
        CP_COMMIT();
    };

    issue_chunk(0);

    for (int c = 0; c < 8; c++) {
        CP_WAIT0();
        __syncthreads();
        if (c < 7) issue_chunk(c + 1);

        const int buf = c & 1;
        const uint32_t* Asu = (const uint32_t*)(smf + buf * PJ_BUF_FLOATS);
        const uint32_t* Bsu = Asu + PJ_A_FLOATS;
        const int a_base = (o0 + g) * PJ_AS + tig;
        const int b_base = (nb + g) * PJ_AS + tig;

        #pragma unroll
        for (int k8 = 0; k8 < 32; k8 += 8) {
            uint32_t a[4][4];
            #pragma unroll
            for (int mi = 0; mi < 4; mi++) {
                int ab = a_base + mi * (16 * PJ_AS) + k8;
                a[mi][0] = Asu[ab];
                a[mi][1] = Asu[ab + 8 * PJ_AS];
                a[mi][2] = Asu[ab + 4];
                a[mi][3] = Asu[ab + 8 * PJ_AS + 4];
            }
            uint32_t bfr[8][2];
            #pragma unroll
            for (int ni = 0; ni < 8; ni++) {
                int bb = b_base + ni * (8 * PJ_AS) + k8;
                bfr[ni][0] = Bsu[bb];
                bfr[ni][1] = Bsu[bb + 4];
            }
            #pragma unroll
            for (int mi = 0; mi < 4; mi++)
                #pragma unroll
                for (int ni = 0; ni < 8; ni++)
                    mma_tf32(acc[mi][ni], a[mi], bfr[ni]);
        }
        __syncthreads();
    }

    float* Ssm = smf;
    #pragma unroll
    for (int h = 0; h < 2; h++) {
        __syncthreads();
        if ((wid >> 2) == h) {
            #pragma unroll
            for (int mi = 0; mi < 4; mi++) {
                int orow = o0 + mi * 16 + g;
                #pragma unroll
                for (int ni = 0; ni < 8; ni++) {
                    int nl = ni * 8 + 2 * tig;
                    *(float2*)&Ssm[orow * 68 + nl] =
                        make_float2(acc[mi][ni][0], acc[mi][ni][1]);
                    *(float2*)&Ssm[(orow + 8) * 68 + nl] =
                        make_float2(acc[mi][ni][2], acc[mi][ni][3]);
                }
            }
        }
        __syncthreads();
        #pragma unroll 4
        for (int it = 0; it < 64; it++) {
            int idx = it * 256 + tid;
            int o = idx >> 6, nn = idx & 63;
            float v = Ssm[o * 68 + nn];
            v = v * proj_scale[o] + proj_bias[o];
            unsigned ng = (unsigned)(n0 + h * 64 + nn);
            unsigned bb = ng / 196u;
            unsigned pp = ng - bb * 196u;
            out[(size_t)bb * (DIM * NPIX) + (size_t)o * NPIX + pp] = v;
        }
    }
}

extern "C" void kernel_launch(void* const* d_in, const int* in_sizes, int n_in,
                              void* d_out, int out_size)
{
    (void)in_sizes; (void)n_in; (void)out_size;
    const float* x          = (const float*)d_in[0];
    const float* qkv_w      = (const float*)d_in[1];
    const float* qkv_scale  = (const float*)d_in[2];
    const float* qkv_bias   = (const float*)d_in[3];
    const float* dw_w       = (const float*)d_in[4];
    const float* dw_scale   = (const float*)d_in[5];
    const float* dw_bias    = (const float*)d_in[6];
    const float* proj_w     = (const float*)d_in[7];
    const float* proj_scale = (const float*)d_in[8];
    const float* proj_bias  = (const float*)d_in[9];
    const float* attn_b     = (const float*)d_in[10];
    const int*   bias_idxs  = (const int*)d_in[11];
    float* out = (float*)d_out;

    cudaFuncSetAttribute(cascade_kernel, cudaFuncAttributeMaxDynamicSharedMemorySize, SMEM1_BYTES);
    cudaFuncSetAttribute(proj_mma_kernel, cudaFuncAttributeMaxDynamicSharedMemorySize, PJ_SMEM_BYTES);

    wprep_kernel<<<DIM * DIM / 256, 256>>>(proj_w);
    abprep_kernel<<<(NH * NPIX * NPIX + 255) / 256, 256>>>(attn_b, bias_idxs);
    cascade_kernel<<<BATCH, 1024, SMEM1_BYTES>>>(x, qkv_w, qkv_scale, qkv_bias,
                                                 dw_w, dw_scale, dw_bias);
    proj_mma_kernel<<<(BATCH * NPIX) / PJ_NT, 256, PJ_SMEM_BYTES>>>(proj_scale, proj_bias, out);
}